// round 7
// baseline (speedup 1.0000x reference)
#include <cuda_runtime.h>
#include <cuda_fp16.h>
#include <cstdint>

typedef unsigned long long ull;

#define LOCN   40001
#define BATCH  1024
#define TSTEPS 256

#define ROWS_PER_CTA 7
#define NCTA ((BATCH + ROWS_PER_CTA - 1) / ROWS_PER_CTA)   // 147
#define HSTRIDE 112                          // 4 quarters of 28 floats; real k=25q+i at 28q+i
#define RECW 512                             // scratch record width in halfs (1024 B)
#define SCR_BYTES (ROWS_PER_CTA * RECW * 2)  // 7168, multiple of 16

// ---------------- device scratch ----------------
__device__ __half g_Gloc[(size_t)LOCN * 600];                 // fp16: 48 MB
__device__ float  g_Pt[92 * 100];
__device__ float  g_Ps[92 * 100];
__device__ __half g_scr[(size_t)TSTEPS * BATCH * RECW + 8192]; // fp16 records: 268 MB

// ---------------- helpers ----------------
__device__ __forceinline__ float sigf(float x) { return 1.f / (1.f + __expf(-x)); }
__device__ __forceinline__ float tanh_fast(float x) { return 1.f - 2.f / (1.f + __expf(2.f * x)); }

__device__ __forceinline__ ull pack2(float lo, float hi) {
    ull r; asm("mov.b64 %0, {%1, %2};" : "=l"(r) : "f"(lo), "f"(hi)); return r;
}
__device__ __forceinline__ void unpack2(ull v, float& lo, float& hi) {
    asm("mov.b64 {%0, %1}, %2;" : "=f"(lo), "=f"(hi) : "l"(v));
}
__device__ __forceinline__ void fma2(ull& acc, ull a, ull b) {
    asm("fma.rn.f32x2 %0, %1, %2, %0;" : "+l"(acc) : "l"(a), "l"(b));
}
__device__ __forceinline__ uint32_t smem_u32(const void* p) {
    uint32_t a;
    asm("{ .reg .u64 t; cvta.to.shared.u64 t, %1; cvt.u32.u64 %0, t; }" : "=r"(a) : "l"(p));
    return a;
}
__device__ __forceinline__ void mbar_init(uint32_t mbar, uint32_t cnt) {
    asm volatile("mbarrier.init.shared.b64 [%0], %1;" :: "r"(mbar), "r"(cnt) : "memory");
}
__device__ __forceinline__ void mbar_expect_tx(uint32_t mbar, uint32_t bytes) {
    asm volatile("mbarrier.arrive.expect_tx.shared.b64 _, [%0], %1;" :: "r"(mbar), "r"(bytes) : "memory");
}
__device__ __forceinline__ void bulk_g2s(uint32_t dst, const void* src, uint32_t bytes, uint32_t mbar) {
    asm volatile("cp.async.bulk.shared::cta.global.mbarrier::complete_tx::bytes [%0], [%1], %2, [%3];"
                 :: "r"(dst), "l"(src), "r"(bytes), "r"(mbar) : "memory");
}
__device__ __forceinline__ void mbar_wait(uint32_t mbar, uint32_t parity) {
    uint32_t done;
    asm volatile("{\n\t.reg .pred p;\n\t"
                 "mbarrier.try_wait.parity.acquire.cta.shared::cta.b64 p, [%1], %2;\n\t"
                 "selp.b32 %0, 1, 0, p;\n\t}"
                 : "=r"(done) : "r"(mbar), "r"(parity) : "memory");
    if (!done) {
        asm volatile("{\n\t.reg .pred P1;\n\t"
                     "WL_%=:\n\t"
                     "mbarrier.try_wait.parity.acquire.cta.shared::cta.b64 P1, [%0], %1, 0x989680;\n\t"
                     "@P1 bra.uni WD_%=;\n\t"
                     "bra.uni WL_%=;\n\t"
                     "WD_%=:\n\t}"
                     :: "r"(mbar), "r"(parity) : "memory");
    }
}

// =======================================================================
// Kernel A: Gloc = fp16( emb_loc @ [W_ih|W_xt|W_xs] + biases )
// =======================================================================
__global__ void kernA(const float* __restrict__ emb_loc,
                      const float* __restrict__ W_ih,
                      const float* __restrict__ W_xt,
                      const float* __restrict__ W_xs,
                      const float* __restrict__ b,
                      const float* __restrict__ b_t,
                      const float* __restrict__ b_s)
{
    __shared__ __align__(16) float As[50 * 64];
    __shared__ __align__(16) float Bs[50 * 64];

    const int tid = threadIdx.x;
    const int m0 = blockIdx.x * 64;
    const int n0 = blockIdx.y * 64;
    const int tx = tid & 15, ty = tid >> 4;
    const int r0 = ty * 4, c0 = tx * 4;

    ull acc[4][2];
#pragma unroll
    for (int i = 0; i < 4; i++) { acc[i][0] = 0ull; acc[i][1] = 0ull; }

    for (int kp = 0; kp < 100; kp += 50) {
        for (int i = tid; i < 64 * 50; i += 256) {
            int r = i / 50, k = i % 50;
            int row = m0 + r;
            As[k * 64 + r] = (row < LOCN) ? emb_loc[(size_t)row * 100 + kp + k] : 0.f;
        }
        for (int i = tid; i < 64 * 50; i += 256) {
            int k = i / 64, c = i % 64;
            int col = n0 + c, kk = kp + k;
            float v = 0.f;
            if (col < 400)      v = W_ih[kk * 400 + col];
            else if (col < 500) v = W_xt[kk * 100 + (col - 400)];
            else if (col < 600) v = W_xs[kk * 100 + (col - 500)];
            Bs[k * 64 + c] = v;
        }
        __syncthreads();

#pragma unroll 5
        for (int k = 0; k < 50; k++) {
            float4 a4 = *(const float4*)(As + k * 64 + r0);
            ulonglong2 bv = *(const ulonglong2*)(Bs + k * 64 + c0);
            ull a0 = pack2(a4.x, a4.x);
            ull a1 = pack2(a4.y, a4.y);
            ull a2 = pack2(a4.z, a4.z);
            ull a3 = pack2(a4.w, a4.w);
            fma2(acc[0][0], a0, bv.x); fma2(acc[0][1], a0, bv.y);
            fma2(acc[1][0], a1, bv.x); fma2(acc[1][1], a1, bv.y);
            fma2(acc[2][0], a2, bv.x); fma2(acc[2][1], a2, bv.y);
            fma2(acc[3][0], a3, bv.x); fma2(acc[3][1], a3, bv.y);
        }
        __syncthreads();
    }

    float bias[4];
#pragma unroll
    for (int p = 0; p < 4; p++) {
        int col = n0 + c0 + p;
        float bv = 0.f;
        if (col < 400)      bv = b[col];
        else if (col < 500) bv = b_t[col - 400];
        else if (col < 600) bv = b_s[col - 500];
        bias[p] = bv;
    }
    const int colg = n0 + c0;                // group of 4 cols, all valid iff colg < 600
#pragma unroll
    for (int r = 0; r < 4; r++) {
        int row = m0 + r0 + r;
        if (row >= LOCN || colg >= 600) continue;
        float v0, v1, v2, v3;
        unpack2(acc[r][0], v0, v1);
        unpack2(acc[r][1], v2, v3);
        __half2 h01 = __floats2half2_rn(v0 + bias[0], v1 + bias[1]);
        __half2 h23 = __floats2half2_rn(v2 + bias[2], v3 + bias[3]);
        uint2 st;
        st.x = *reinterpret_cast<unsigned*>(&h01);
        st.y = *reinterpret_cast<unsigned*>(&h23);
        *reinterpret_cast<uint2*>(&g_Gloc[(size_t)row * 600 + colg]) = st;
    }
}

// =======================================================================
// Kernel B: P_t = emb_t @ W_tt ; P_s = emb_s @ W_ss  (fp32, tiny)
// =======================================================================
__global__ void kernB(const float* __restrict__ emb_t, const float* __restrict__ W_tt,
                      const float* __restrict__ emb_s, const float* __restrict__ W_ss)
{
    int i = blockIdx.x * blockDim.x + threadIdx.x;
    if (i >= 92 * 100 * 2) return;
    int which = i / 9200;
    int r = i % 9200;
    int s = r / 100, j = r % 100;
    const float* e = which ? emb_s : emb_t;
    const float* W = which ? W_ss : W_tt;
    float acc = 0.f;
#pragma unroll
    for (int d = 0; d < 12; d++) acc += e[s * 12 + d] * W[d * 100 + j];
    (which ? g_Ps : g_Pt)[s * 100 + j] = acc;
}

// =======================================================================
// Kernel C: copy 400 fp16 preacts + compute tsg -> fp16 record [512]
// One warp per token.
// =======================================================================
__global__ void kernC(const int* __restrict__ traj,
                      const int* __restrict__ tu, const int* __restrict__ tl,
                      const int* __restrict__ tu_slot, const int* __restrict__ tl_slot,
                      const int* __restrict__ su, const int* __restrict__ sl,
                      const int* __restrict__ su_slot, const int* __restrict__ sl_slot)
{
    const int w = threadIdx.x >> 5, lane = threadIdx.x & 31;
    const int token = blockIdx.x * 8 + w;
    const int bb = token >> 8, t = token & 255;

    const int idx = traj[token];
    const __half* gh = g_Gloc + (size_t)idx * 600;
    __half* sh = g_scr + ((size_t)t * BATCH + bb) * RECW;

    // copy 400 preact halfs (800 B) as uint4
    {
        const uint4* gv = (const uint4*)gh;   // 600 halfs = 75 uint4; first 50 = preacts
        uint4* ov = (uint4*)sh;
        for (int q = lane; q < 50; q += 32) ov[q] = gv[q];
    }

    if (lane < 25) {
        const float ut = (float)tu_slot[token], lt = (float)tl_slot[token];
        const float us = (float)su_slot[token], ls = (float)sl_slot[token];
        const float rdt = 1.f / fmaxf(ut + lt, 1.f);
        const float rds = 1.f / fmaxf(us + ls, 1.f);
        const float* Ptl = g_Pt + tl[token] * 100;
        const float* Ptu = g_Pt + tu[token] * 100;
        const float* Psl = g_Ps + sl[token] * 100;
        const float* Psu = g_Ps + su[token] * 100;

        const int j0 = lane * 4;
        float ts[4];
#pragma unroll
        for (int k = 0; k < 4; k++) {
            int j = j0 + k;
            float pt = __half2float(gh[400 + j]) + (ut * Ptl[j] + lt * Ptu[j]) * rdt;
            float ps = __half2float(gh[500 + j]) + (us * Psl[j] + ls * Psu[j]) * rds;
            ts[k] = sigf(pt) * sigf(ps);
        }
        __half2 h01 = __floats2half2_rn(ts[0], ts[1]);
        __half2 h23 = __floats2half2_rn(ts[2], ts[3]);
        uint2 st;
        st.x = *reinterpret_cast<unsigned*>(&h01);
        st.y = *reinterpret_cast<unsigned*>(&h23);
        reinterpret_cast<uint2*>(sh + 400)[lane] = st;
    }
}

// =======================================================================
// Kernel D v7: 4-gate column ownership within one warp. 800 threads.
//  tid = j*8 + u : j in [0,100); u = half*4 + q (half: gate pair, q: k-quarter)
//   u 0,1,2,3 -> cols {j, j+200} (gates i,g), k-quarters q=u
//   u 4,5,6,7 -> cols {j+100, j+300} (gates f,o)
//  Mainloop identical to v6 (28 ull weights, 7 LDS.128, 28 FFMA2, 2-shfl RS).
//  After RS: lanes u=0->i, 2->g, 4->f, 6->o (full sums). Parallel branch-free
//  activation (tsg folded into g). 3 shfl.idx(width 8) gather to lane u=0,
//  which updates c (smem, exclusive) and writes h. ONE barrier per step.
//  fp16 scratch staged 2 steps ahead via cp.async.bulk.
// =======================================================================
__global__ void __launch_bounds__(800, 1)
kernD(const float* __restrict__ W_hh, float* __restrict__ out)
{
    __shared__ __align__(16) float  hbuf[2][ROWS_PER_CTA][HSTRIDE];
    __shared__ __align__(16) float  cbuf[ROWS_PER_CTA][100];
    __shared__ __align__(16) __half sscr[2][ROWS_PER_CTA * RECW];
    __shared__ __align__(8)  ull    smbar[2];

    const int tid = threadIdx.x;
    const int j = tid >> 3, u = tid & 7;
    const int q = u & 3, half = u >> 2;
    const int row0 = blockIdx.x * ROWS_PER_CTA;

    const int colA = j + 100 * half;         // gate i (half0) or f (half1)
    const int colB = colA + 200;             // gate g (half0) or o (half1)
    const int mycol = (u & 2) ? colB : colA;
    const bool isg = (u == 2) || (u == 3);   // tanh gate
    const float ascale = isg ? 2.f : 1.f;
    const float aA     = isg ? 2.f : 1.f;
    const float aB     = isg ? -1.f : 0.f;

    const int hslot = 28 * (j / 25) + (j % 25);   // padded slot for h[j]

    // ---- weights: 14 (k,k+1) pairs per column, k-range = quarter q ----
    ull wA[14], wB[14];
#pragma unroll
    for (int m = 0; m < 14; m++) {
        int i0 = 2 * m, i1 = 2 * m + 1;
        float a0 = 0.f, a1 = 0.f, b0 = 0.f, b1 = 0.f;
        if (i0 < 25) {
            int k = 25 * q + i0;
            a0 = W_hh[k * 400 + colA];
            b0 = W_hh[k * 400 + colB];
        }
        if (i1 < 25) {
            int k = 25 * q + i1;
            a1 = W_hh[k * 400 + colA];
            b1 = W_hh[k * 400 + colB];
        }
        wA[m] = pack2(a0, a1);
        wB[m] = pack2(b0, b1);
    }

    // ---- init smem ----
    {
        float* pp = &hbuf[0][0][0];
        for (int i = tid; i < 2 * ROWS_PER_CTA * HSTRIDE; i += 800) pp[i] = 0.f;
        float* pc = &cbuf[0][0];
        for (int i = tid; i < ROWS_PER_CTA * 100; i += 800) pc[i] = 0.f;
    }
    uint32_t mb0 = smem_u32(&smbar[0]);
    uint32_t mb1 = smem_u32(&smbar[1]);
    uint32_t sc0 = smem_u32(&sscr[0][0]);
    uint32_t sc1 = smem_u32(&sscr[1][0]);
    if (tid == 0) { mbar_init(mb0, 1); mbar_init(mb1, 1); }
    __syncthreads();

    const __half* scr_base = g_scr + (size_t)row0 * RECW;
    if (tid == 0) {
        mbar_expect_tx(mb0, SCR_BYTES);
        bulk_g2s(sc0, scr_base, SCR_BYTES, mb0);
        mbar_expect_tx(mb1, SCR_BYTES);
        bulk_g2s(sc1, scr_base + (size_t)BATCH * RECW, SCR_BYTES, mb1);
    }

#pragma unroll 1
    for (int t = 0; t < TSTEPS; t++) {
        const int buf = t & 1;
        mbar_wait(buf ? mb1 : mb0, (t >> 1) & 1);

        const __half* sbh = sscr[buf];
        const float* hc = &hbuf[buf][0][0];
        float* hn = &hbuf[buf ^ 1][0][0];

#pragma unroll
        for (int r = 0; r < ROWS_PER_CTA; r++) {
            // per-lane preact for its column; g lanes also fetch tsg
            float pre = __half2float(sbh[r * RECW + mycol]);
            float tmul = isg ? __half2float(sbh[r * RECW + 400 + j]) : 1.f;

            const ulonglong2* h2 = (const ulonglong2*)(hc + r * HSTRIDE + q * 28);
            ull aaA = 0ull, aaB = 0ull;
#pragma unroll
            for (int m = 0; m < 7; m++) {
                ulonglong2 hv = h2[m];
                fma2(aaA, hv.x, wA[2 * m]);
                fma2(aaB, hv.x, wB[2 * m]);
                fma2(aaA, hv.y, wA[2 * m + 1]);
                fma2(aaB, hv.y, wB[2 * m + 1]);
            }
            float xl, xh, sA, sB;
            unpack2(aaA, xl, xh); sA = xl + xh;
            unpack2(aaB, xl, xh); sB = xl + xh;

            // reduce-scatter over the 4 q-lanes (within each half)
            float tsend = (q & 2) ? sA : sB;
            float trecv = __shfl_xor_sync(0xffffffffu, tsend, 2);
            float v = ((q & 2) ? sB : sA) + trecv;
            v += __shfl_xor_sync(0xffffffffu, v, 1);
            // u=0,1 -> colA sum ; u=2,3 -> colB sum (per half)

            v += pre;
            float s = 1.f / (1.f + __expf(-ascale * v));
            float act = fmaf(s, aA, aB) * tmul;   // i/f/o: sig ; g: tanh*tsg

            // gather gates to lane u=0 of each 8-group
            float vg = __shfl_sync(0xffffffffu, act, 2, 8);
            float vf = __shfl_sync(0xffffffffu, act, 4, 8);
            float vo = __shfl_sync(0xffffffffu, act, 6, 8);

            if (u == 0) {
                float c = cbuf[r][j];
                float cN = vf * c + act * vg;      // act = gi
                cbuf[r][j] = cN;
                float h = vo * tanh_fast(cN);
                hn[r * HSTRIDE + hslot] = h;
                if (t == TSTEPS - 1 && row0 + r < BATCH) out[(row0 + r) * 100 + j] = h;
            }
        }
        __syncthreads();

        if (t + 2 < TSTEPS && tid == 0) {
            uint32_t mb = buf ? mb1 : mb0;
            mbar_expect_tx(mb, SCR_BYTES);
            bulk_g2s(buf ? sc1 : sc0, scr_base + (size_t)(t + 2) * BATCH * RECW, SCR_BYTES, mb);
        }
    }
}

// =======================================================================
// launch
// =======================================================================
extern "C" void kernel_launch(void* const* d_in, const int* in_sizes, int n_in,
                              void* d_out, int out_size)
{
    (void)in_sizes; (void)n_in; (void)out_size;
    const int*   traj    = (const int*)d_in[0];
    const int*   tu      = (const int*)d_in[3];
    const int*   tl      = (const int*)d_in[4];
    const int*   tu_s    = (const int*)d_in[5];
    const int*   tl_s    = (const int*)d_in[6];
    const int*   su      = (const int*)d_in[7];
    const int*   sl      = (const int*)d_in[8];
    const int*   su_s    = (const int*)d_in[9];
    const int*   sl_s    = (const int*)d_in[10];
    const float* emb_loc = (const float*)d_in[11];
    const float* emb_t   = (const float*)d_in[12];
    const float* emb_s   = (const float*)d_in[13];
    const float* W_ih    = (const float*)d_in[14];
    const float* W_hh    = (const float*)d_in[15];
    const float* b       = (const float*)d_in[16];
    const float* W_xt    = (const float*)d_in[17];
    const float* W_tt    = (const float*)d_in[18];
    const float* b_t     = (const float*)d_in[19];
    const float* W_xs    = (const float*)d_in[20];
    const float* W_ss    = (const float*)d_in[21];
    const float* b_s     = (const float*)d_in[22];
    float* out = (float*)d_out;

    dim3 gA((LOCN + 63) / 64, 10);
    kernA<<<gA, 256>>>(emb_loc, W_ih, W_xt, W_xs, b, b_t, b_s);

    kernB<<<(92 * 100 * 2 + 255) / 256, 256>>>(emb_t, W_tt, emb_s, W_ss);

    kernC<<<(BATCH * TSTEPS) / 8, 256>>>(traj, tu, tl, tu_s, tl_s, su, sl, su_s, sl_s);

    kernD<<<NCTA, 800>>>(W_hh, out);
}

// round 8
// speedup vs baseline: 1.1554x; 1.1554x over previous
#include <cuda_runtime.h>
#include <cuda_fp16.h>
#include <cstdint>

typedef unsigned long long ull;

#define LOCN   40001
#define BATCH  1024
#define TSTEPS 256

#define ROWS_PER_CTA 7
#define NCTA ((BATCH + ROWS_PER_CTA - 1) / ROWS_PER_CTA)   // 147
#define HSTRIDE 112                          // 4 quarters of 28 floats; real k=25q+i at 28q+i
#define RECW 512                             // scratch record width in halfs (1024 B)
#define SCR_BYTES (ROWS_PER_CTA * RECW * 2)  // 7168, multiple of 16

// ---------------- device scratch ----------------
__device__ __half g_Gloc[(size_t)LOCN * 600];                  // fp16: 48 MB
__device__ float  g_Pt[92 * 100];
__device__ float  g_Ps[92 * 100];
__device__ __half g_scr[(size_t)TSTEPS * BATCH * RECW + 8192]; // fp16 records: 268 MB

// ---------------- helpers ----------------
__device__ __forceinline__ float sigf(float x) { return 1.f / (1.f + __expf(-x)); }
__device__ __forceinline__ float tanh_fast(float x) { return 1.f - 2.f / (1.f + __expf(2.f * x)); }

__device__ __forceinline__ ull pack2(float lo, float hi) {
    ull r; asm("mov.b64 %0, {%1, %2};" : "=l"(r) : "f"(lo), "f"(hi)); return r;
}
__device__ __forceinline__ void unpack2(ull v, float& lo, float& hi) {
    asm("mov.b64 {%0, %1}, %2;" : "=f"(lo), "=f"(hi) : "l"(v));
}
__device__ __forceinline__ void fma2(ull& acc, ull a, ull b) {
    asm("fma.rn.f32x2 %0, %1, %2, %0;" : "+l"(acc) : "l"(a), "l"(b));
}
__device__ __forceinline__ uint32_t smem_u32(const void* p) {
    uint32_t a;
    asm("{ .reg .u64 t; cvta.to.shared.u64 t, %1; cvt.u32.u64 %0, t; }" : "=r"(a) : "l"(p));
    return a;
}
__device__ __forceinline__ void mbar_init(uint32_t mbar, uint32_t cnt) {
    asm volatile("mbarrier.init.shared.b64 [%0], %1;" :: "r"(mbar), "r"(cnt) : "memory");
}
__device__ __forceinline__ void mbar_expect_tx(uint32_t mbar, uint32_t bytes) {
    asm volatile("mbarrier.arrive.expect_tx.shared.b64 _, [%0], %1;" :: "r"(mbar), "r"(bytes) : "memory");
}
__device__ __forceinline__ void bulk_g2s(uint32_t dst, const void* src, uint32_t bytes, uint32_t mbar) {
    asm volatile("cp.async.bulk.shared::cta.global.mbarrier::complete_tx::bytes [%0], [%1], %2, [%3];"
                 :: "r"(dst), "l"(src), "r"(bytes), "r"(mbar) : "memory");
}
__device__ __forceinline__ void mbar_wait(uint32_t mbar, uint32_t parity) {
    uint32_t done;
    asm volatile("{\n\t.reg .pred p;\n\t"
                 "mbarrier.try_wait.parity.acquire.cta.shared::cta.b64 p, [%1], %2;\n\t"
                 "selp.b32 %0, 1, 0, p;\n\t}"
                 : "=r"(done) : "r"(mbar), "r"(parity) : "memory");
    if (!done) {
        asm volatile("{\n\t.reg .pred P1;\n\t"
                     "WL_%=:\n\t"
                     "mbarrier.try_wait.parity.acquire.cta.shared::cta.b64 P1, [%0], %1, 0x989680;\n\t"
                     "@P1 bra.uni WD_%=;\n\t"
                     "bra.uni WL_%=;\n\t"
                     "WD_%=:\n\t}"
                     :: "r"(mbar), "r"(parity) : "memory");
    }
}

// =======================================================================
// Kernel A: Gloc = fp16( emb_loc @ [W_ih|W_xt|W_xs] + biases )
// =======================================================================
__global__ void kernA(const float* __restrict__ emb_loc,
                      const float* __restrict__ W_ih,
                      const float* __restrict__ W_xt,
                      const float* __restrict__ W_xs,
                      const float* __restrict__ b,
                      const float* __restrict__ b_t,
                      const float* __restrict__ b_s)
{
    __shared__ __align__(16) float As[50 * 64];
    __shared__ __align__(16) float Bs[50 * 64];

    const int tid = threadIdx.x;
    const int m0 = blockIdx.x * 64;
    const int n0 = blockIdx.y * 64;
    const int tx = tid & 15, ty = tid >> 4;
    const int r0 = ty * 4, c0 = tx * 4;

    ull acc[4][2];
#pragma unroll
    for (int i = 0; i < 4; i++) { acc[i][0] = 0ull; acc[i][1] = 0ull; }

    for (int kp = 0; kp < 100; kp += 50) {
        for (int i = tid; i < 64 * 50; i += 256) {
            int r = i / 50, k = i % 50;
            int row = m0 + r;
            As[k * 64 + r] = (row < LOCN) ? emb_loc[(size_t)row * 100 + kp + k] : 0.f;
        }
        for (int i = tid; i < 64 * 50; i += 256) {
            int k = i / 64, c = i % 64;
            int col = n0 + c, kk = kp + k;
            float v = 0.f;
            if (col < 400)      v = W_ih[kk * 400 + col];
            else if (col < 500) v = W_xt[kk * 100 + (col - 400)];
            else if (col < 600) v = W_xs[kk * 100 + (col - 500)];
            Bs[k * 64 + c] = v;
        }
        __syncthreads();

#pragma unroll 5
        for (int k = 0; k < 50; k++) {
            float4 a4 = *(const float4*)(As + k * 64 + r0);
            ulonglong2 bv = *(const ulonglong2*)(Bs + k * 64 + c0);
            ull a0 = pack2(a4.x, a4.x);
            ull a1 = pack2(a4.y, a4.y);
            ull a2 = pack2(a4.z, a4.z);
            ull a3 = pack2(a4.w, a4.w);
            fma2(acc[0][0], a0, bv.x); fma2(acc[0][1], a0, bv.y);
            fma2(acc[1][0], a1, bv.x); fma2(acc[1][1], a1, bv.y);
            fma2(acc[2][0], a2, bv.x); fma2(acc[2][1], a2, bv.y);
            fma2(acc[3][0], a3, bv.x); fma2(acc[3][1], a3, bv.y);
        }
        __syncthreads();
    }

    float bias[4];
#pragma unroll
    for (int p = 0; p < 4; p++) {
        int col = n0 + c0 + p;
        float bv = 0.f;
        if (col < 400)      bv = b[col];
        else if (col < 500) bv = b_t[col - 400];
        else if (col < 600) bv = b_s[col - 500];
        bias[p] = bv;
    }
    const int colg = n0 + c0;                // group of 4 cols, all valid iff colg < 600
#pragma unroll
    for (int r = 0; r < 4; r++) {
        int row = m0 + r0 + r;
        if (row >= LOCN || colg >= 600) continue;
        float v0, v1, v2, v3;
        unpack2(acc[r][0], v0, v1);
        unpack2(acc[r][1], v2, v3);
        __half2 h01 = __floats2half2_rn(v0 + bias[0], v1 + bias[1]);
        __half2 h23 = __floats2half2_rn(v2 + bias[2], v3 + bias[3]);
        uint2 st;
        st.x = *reinterpret_cast<unsigned*>(&h01);
        st.y = *reinterpret_cast<unsigned*>(&h23);
        *reinterpret_cast<uint2*>(&g_Gloc[(size_t)row * 600 + colg]) = st;
    }
}

// =======================================================================
// Kernel B: P_t = emb_t @ W_tt ; P_s = emb_s @ W_ss  (fp32, tiny)
// =======================================================================
__global__ void kernB(const float* __restrict__ emb_t, const float* __restrict__ W_tt,
                      const float* __restrict__ emb_s, const float* __restrict__ W_ss)
{
    int i = blockIdx.x * blockDim.x + threadIdx.x;
    if (i >= 92 * 100 * 2) return;
    int which = i / 9200;
    int r = i % 9200;
    int s = r / 100, j = r % 100;
    const float* e = which ? emb_s : emb_t;
    const float* W = which ? W_ss : W_tt;
    float acc = 0.f;
#pragma unroll
    for (int d = 0; d < 12; d++) acc += e[s * 12 + d] * W[d * 100 + j];
    (which ? g_Ps : g_Pt)[s * 100 + j] = acc;
}

// =======================================================================
// Kernel C: copy 400 fp16 preacts + compute tsg -> fp16 record [512]
// One warp per token.
// =======================================================================
__global__ void kernC(const int* __restrict__ traj,
                      const int* __restrict__ tu, const int* __restrict__ tl,
                      const int* __restrict__ tu_slot, const int* __restrict__ tl_slot,
                      const int* __restrict__ su, const int* __restrict__ sl,
                      const int* __restrict__ su_slot, const int* __restrict__ sl_slot)
{
    const int w = threadIdx.x >> 5, lane = threadIdx.x & 31;
    const int token = blockIdx.x * 8 + w;
    const int bb = token >> 8, t = token & 255;

    const int idx = traj[token];
    const __half* gh = g_Gloc + (size_t)idx * 600;
    __half* sh = g_scr + ((size_t)t * BATCH + bb) * RECW;

    // copy 400 preact halfs (800 B) as uint4
    {
        const uint4* gv = (const uint4*)gh;   // first 50 uint4 = 400 preact halfs
        uint4* ov = (uint4*)sh;
        for (int q = lane; q < 50; q += 32) ov[q] = gv[q];
    }

    if (lane < 25) {
        const float ut = (float)tu_slot[token], lt = (float)tl_slot[token];
        const float us = (float)su_slot[token], ls = (float)sl_slot[token];
        const float rdt = 1.f / fmaxf(ut + lt, 1.f);
        const float rds = 1.f / fmaxf(us + ls, 1.f);
        const float* Ptl = g_Pt + tl[token] * 100;
        const float* Ptu = g_Pt + tu[token] * 100;
        const float* Psl = g_Ps + sl[token] * 100;
        const float* Psu = g_Ps + su[token] * 100;

        const int j0 = lane * 4;
        float ts[4];
#pragma unroll
        for (int k = 0; k < 4; k++) {
            int j = j0 + k;
            float pt = __half2float(gh[400 + j]) + (ut * Ptl[j] + lt * Ptu[j]) * rdt;
            float ps = __half2float(gh[500 + j]) + (us * Psl[j] + ls * Psu[j]) * rds;
            ts[k] = sigf(pt) * sigf(ps);
        }
        __half2 h01 = __floats2half2_rn(ts[0], ts[1]);
        __half2 h23 = __floats2half2_rn(ts[2], ts[3]);
        uint2 st;
        st.x = *reinterpret_cast<unsigned*>(&h01);
        st.y = *reinterpret_cast<unsigned*>(&h23);
        reinterpret_cast<uint2*>(sh + 400)[lane] = st;
    }
}

// =======================================================================
// Kernel D v8: v6 structure (column-pair + 4-way k split, acts in smem,
// two barriers) with fp16 scratch. 800 threads.
//  tid = p*4 + q : p in [0,200) owns columns {p, p+200}; q = k-quarter.
//  h padded to 112: real k = 25*qq + i stored at 28*qq + i (pads stay 0).
//  Per thread-row: 7 LDS.128 -> 28 FFMA2, 2-shfl reduce-scatter,
//  branch-free activation on lanes q=0/q=2, STS into acts.
//  Phase 2: 700 (r,j) items, c in regs.
//  fp16 scratch staged 2 steps ahead via cp.async.bulk (7 KB/step).
// =======================================================================
__global__ void __launch_bounds__(800, 1)
kernD(const float* __restrict__ W_hh, float* __restrict__ out)
{
    __shared__ __align__(16) float  hbuf[2][ROWS_PER_CTA][HSTRIDE];
    __shared__ __align__(16) float  acts[ROWS_PER_CTA][400];
    __shared__ __align__(16) __half sscr[2][ROWS_PER_CTA * RECW];
    __shared__ __align__(8)  ull    smbar[2];

    const int tid = threadIdx.x;
    const int p = tid >> 2, q = tid & 3;     // column pair {p, p+200}, k-quarter
    const int row0 = blockIdx.x * ROWS_PER_CTA;

    // this lane's output column after reduce-scatter (lanes q<2 -> p, q>=2 -> p+200)
    const int mycol = p + ((q & 2) ? 200 : 0);
    const int mygate = mycol / 100;          // 0:i 1:f 2:g 3:o
    const float ascale = (mygate == 2) ? 2.f : 1.f;
    const float aA     = (mygate == 2) ? 2.f : 1.f;
    const float aB     = (mygate == 2) ? -1.f : 0.f;
    const bool doST = ((q & 1) == 0);        // lanes 0 and 2 store

    // phase-2 assignment (loop-invariant)
    const int r_2 = tid / 100, j_2 = tid % 100;
    const bool p2act = (tid < 700);
    const int hslot_2 = 28 * (j_2 / 25) + (j_2 % 25);   // padded h offset for j_2
    const bool p2out = (row0 + r_2 < BATCH);

    // ---- weights: 14 (k,k+1) pairs per column, k-range = quarter q ----
    ull wA[14], wB[14];
#pragma unroll
    for (int m = 0; m < 14; m++) {
        int i0 = 2 * m, i1 = 2 * m + 1;
        float a0 = 0.f, a1 = 0.f, b0 = 0.f, b1 = 0.f;
        if (i0 < 25) {
            int k = 25 * q + i0;
            a0 = W_hh[k * 400 + p];
            b0 = W_hh[k * 400 + p + 200];
        }
        if (i1 < 25) {
            int k = 25 * q + i1;
            a1 = W_hh[k * 400 + p];
            b1 = W_hh[k * 400 + p + 200];
        }
        wA[m] = pack2(a0, a1);
        wB[m] = pack2(b0, b1);
    }

    // ---- init smem ----
    {
        float* pp = &hbuf[0][0][0];
        for (int i = tid; i < 2 * ROWS_PER_CTA * HSTRIDE; i += 800) pp[i] = 0.f;
    }
    uint32_t mb0 = smem_u32(&smbar[0]);
    uint32_t mb1 = smem_u32(&smbar[1]);
    uint32_t sc0 = smem_u32(&sscr[0][0]);
    uint32_t sc1 = smem_u32(&sscr[1][0]);
    if (tid == 0) { mbar_init(mb0, 1); mbar_init(mb1, 1); }
    __syncthreads();

    const __half* scr_base = g_scr + (size_t)row0 * RECW;
    if (tid == 0) {
        mbar_expect_tx(mb0, SCR_BYTES);
        bulk_g2s(sc0, scr_base, SCR_BYTES, mb0);
        mbar_expect_tx(mb1, SCR_BYTES);
        bulk_g2s(sc1, scr_base + (size_t)BATCH * RECW, SCR_BYTES, mb1);
    }

    float creg = 0.f;                        // cell state for phase-2 item

#pragma unroll 1
    for (int t = 0; t < TSTEPS; t++) {
        const int buf = t & 1;
        mbar_wait(buf ? mb1 : mb0, (t >> 1) & 1);

        const __half* sbh = sscr[buf];
        const float* hc = &hbuf[buf][0][0];
        float* hn = &hbuf[buf ^ 1][0][0];

        // ---------------- phase 1: gate pre-sums + activations ----------------
#pragma unroll
        for (int r = 0; r < ROWS_PER_CTA; r++) {
            const ulonglong2* h2 = (const ulonglong2*)(hc + r * HSTRIDE + q * 28);
            ull aaA = 0ull, aaB = 0ull;
#pragma unroll
            for (int m = 0; m < 7; m++) {
                ulonglong2 hv = h2[m];
                fma2(aaA, hv.x, wA[2 * m]);
                fma2(aaB, hv.x, wB[2 * m]);
                fma2(aaA, hv.y, wA[2 * m + 1]);
                fma2(aaB, hv.y, wB[2 * m + 1]);
            }
            float xl, xh, sA, sB;
            unpack2(aaA, xl, xh); sA = xl + xh;
            unpack2(aaB, xl, xh); sB = xl + xh;

            // reduce-scatter over the 4 q-lanes
            float tsend = (q & 2) ? sA : sB;
            float trecv = __shfl_xor_sync(0xffffffffu, tsend, 2);
            float v = ((q & 2) ? sB : sA) + trecv;
            v += __shfl_xor_sync(0xffffffffu, v, 1);
            // lanes q in {0,1}: full sum col p ; q in {2,3}: full sum col p+200

            v += __half2float(sbh[r * RECW + mycol]);
            float s = 1.f / (1.f + __expf(-ascale * v));
            float act = fmaf(s, aA, aB);
            if (doST) acts[r][mycol] = act;
        }
        __syncthreads();

        // ---------------- phase 2: c/h update ----------------
        if (p2act) {
            const float* ap = &acts[r_2][0];
            float gi = ap[j_2], gf = ap[100 + j_2], gg = ap[200 + j_2], go = ap[300 + j_2];
            float tsg = __half2float(sbh[r_2 * RECW + 400 + j_2]);
            float cN = gf * creg + gi * tsg * gg;
            creg = cN;
            float h = go * tanh_fast(cN);
            hn[r_2 * HSTRIDE + hslot_2] = h;
            if (t == TSTEPS - 1 && p2out) out[(row0 + r_2) * 100 + j_2] = h;
        }
        __syncthreads();

        if (t + 2 < TSTEPS && tid == 0) {
            uint32_t mb = buf ? mb1 : mb0;
            mbar_expect_tx(mb, SCR_BYTES);
            bulk_g2s(buf ? sc1 : sc0, scr_base + (size_t)(t + 2) * BATCH * RECW, SCR_BYTES, mb);
        }
    }
}

// =======================================================================
// launch
// =======================================================================
extern "C" void kernel_launch(void* const* d_in, const int* in_sizes, int n_in,
                              void* d_out, int out_size)
{
    (void)in_sizes; (void)n_in; (void)out_size;
    const int*   traj    = (const int*)d_in[0];
    const int*   tu      = (const int*)d_in[3];
    const int*   tl      = (const int*)d_in[4];
    const int*   tu_s    = (const int*)d_in[5];
    const int*   tl_s    = (const int*)d_in[6];
    const int*   su      = (const int*)d_in[7];
    const int*   sl      = (const int*)d_in[8];
    const int*   su_s    = (const int*)d_in[9];
    const int*   sl_s    = (const int*)d_in[10];
    const float* emb_loc = (const float*)d_in[11];
    const float* emb_t   = (const float*)d_in[12];
    const float* emb_s   = (const float*)d_in[13];
    const float* W_ih    = (const float*)d_in[14];
    const float* W_hh    = (const float*)d_in[15];
    const float* b       = (const float*)d_in[16];
    const float* W_xt    = (const float*)d_in[17];
    const float* W_tt    = (const float*)d_in[18];
    const float* b_t     = (const float*)d_in[19];
    const float* W_xs    = (const float*)d_in[20];
    const float* W_ss    = (const float*)d_in[21];
    const float* b_s     = (const float*)d_in[22];
    float* out = (float*)d_out;

    dim3 gA((LOCN + 63) / 64, 10);
    kernA<<<gA, 256>>>(emb_loc, W_ih, W_xt, W_xs, b, b_t, b_s);

    kernB<<<(92 * 100 * 2 + 255) / 256, 256>>>(emb_t, W_tt, emb_s, W_ss);

    kernC<<<(BATCH * TSTEPS) / 8, 256>>>(traj, tu, tl, tu_s, tl_s, su, sl, su_s, sl_s);

    kernD<<<NCTA, 800>>>(W_hh, out);
}

// round 9
// speedup vs baseline: 1.2053x; 1.0432x over previous
#include <cuda_runtime.h>
#include <cuda_fp16.h>
#include <cstdint>

typedef unsigned long long ull;

#define LOCN   40001
#define BATCH  1024
#define TSTEPS 256

#define ROWS_PER_CTA 7
#define NCTA ((BATCH + ROWS_PER_CTA - 1) / ROWS_PER_CTA)   // 147
#define HSTRIDE 112                          // 4 quarters of 28 floats; real k=25q+i at 28q+i
#define RECW 512                             // scratch record width in halfs (1024 B)
#define SCR_BYTES (ROWS_PER_CTA * RECW * 2)  // 7168, multiple of 16

// ---------------- device scratch ----------------
__device__ __half g_Gloc[(size_t)LOCN * 600];                  // fp16: 48 MB
__device__ float  g_Pt[92 * 100];
__device__ float  g_Ps[92 * 100];
__device__ __half g_scr[(size_t)TSTEPS * BATCH * RECW + 8192]; // fp16 records: 268 MB

// ---------------- helpers ----------------
__device__ __forceinline__ float sigf(float x) { return 1.f / (1.f + __expf(-x)); }
__device__ __forceinline__ float tanh_fast(float x) { return 1.f - 2.f / (1.f + __expf(2.f * x)); }

__device__ __forceinline__ ull pack2(float lo, float hi) {
    ull r; asm("mov.b64 %0, {%1, %2};" : "=l"(r) : "f"(lo), "f"(hi)); return r;
}
__device__ __forceinline__ void unpack2(ull v, float& lo, float& hi) {
    asm("mov.b64 {%0, %1}, %2;" : "=f"(lo), "=f"(hi) : "l"(v));
}
__device__ __forceinline__ void fma2(ull& acc, ull a, ull b) {
    asm("fma.rn.f32x2 %0, %1, %2, %0;" : "+l"(acc) : "l"(a), "l"(b));
}
__device__ __forceinline__ uint32_t smem_u32(const void* p) {
    uint32_t a;
    asm("{ .reg .u64 t; cvta.to.shared.u64 t, %1; cvt.u32.u64 %0, t; }" : "=r"(a) : "l"(p));
    return a;
}
__device__ __forceinline__ void mbar_init(uint32_t mbar, uint32_t cnt) {
    asm volatile("mbarrier.init.shared.b64 [%0], %1;" :: "r"(mbar), "r"(cnt) : "memory");
}
__device__ __forceinline__ void mbar_expect_tx(uint32_t mbar, uint32_t bytes) {
    asm volatile("mbarrier.arrive.expect_tx.shared.b64 _, [%0], %1;" :: "r"(mbar), "r"(bytes) : "memory");
}
__device__ __forceinline__ void bulk_g2s(uint32_t dst, const void* src, uint32_t bytes, uint32_t mbar) {
    asm volatile("cp.async.bulk.shared::cta.global.mbarrier::complete_tx::bytes [%0], [%1], %2, [%3];"
                 :: "r"(dst), "l"(src), "r"(bytes), "r"(mbar) : "memory");
}
__device__ __forceinline__ void mbar_wait(uint32_t mbar, uint32_t parity) {
    uint32_t done;
    asm volatile("{\n\t.reg .pred p;\n\t"
                 "mbarrier.try_wait.parity.acquire.cta.shared::cta.b64 p, [%1], %2;\n\t"
                 "selp.b32 %0, 1, 0, p;\n\t}"
                 : "=r"(done) : "r"(mbar), "r"(parity) : "memory");
    if (!done) {
        asm volatile("{\n\t.reg .pred P1;\n\t"
                     "WL_%=:\n\t"
                     "mbarrier.try_wait.parity.acquire.cta.shared::cta.b64 P1, [%0], %1, 0x989680;\n\t"
                     "@P1 bra.uni WD_%=;\n\t"
                     "bra.uni WL_%=;\n\t"
                     "WD_%=:\n\t}"
                     :: "r"(mbar), "r"(parity) : "memory");
    }
}

// =======================================================================
// Kernel A: Gloc = fp16( emb_loc @ [W_ih|W_xt|W_xs] + biases )
// =======================================================================
__global__ void kernA(const float* __restrict__ emb_loc,
                      const float* __restrict__ W_ih,
                      const float* __restrict__ W_xt,
                      const float* __restrict__ W_xs,
                      const float* __restrict__ b,
                      const float* __restrict__ b_t,
                      const float* __restrict__ b_s)
{
    __shared__ __align__(16) float As[50 * 64];
    __shared__ __align__(16) float Bs[50 * 64];

    const int tid = threadIdx.x;
    const int m0 = blockIdx.x * 64;
    const int n0 = blockIdx.y * 64;
    const int tx = tid & 15, ty = tid >> 4;
    const int r0 = ty * 4, c0 = tx * 4;

    ull acc[4][2];
#pragma unroll
    for (int i = 0; i < 4; i++) { acc[i][0] = 0ull; acc[i][1] = 0ull; }

    for (int kp = 0; kp < 100; kp += 50) {
        for (int i = tid; i < 64 * 50; i += 256) {
            int r = i / 50, k = i % 50;
            int row = m0 + r;
            As[k * 64 + r] = (row < LOCN) ? emb_loc[(size_t)row * 100 + kp + k] : 0.f;
        }
        for (int i = tid; i < 64 * 50; i += 256) {
            int k = i / 64, c = i % 64;
            int col = n0 + c, kk = kp + k;
            float v = 0.f;
            if (col < 400)      v = W_ih[kk * 400 + col];
            else if (col < 500) v = W_xt[kk * 100 + (col - 400)];
            else if (col < 600) v = W_xs[kk * 100 + (col - 500)];
            Bs[k * 64 + c] = v;
        }
        __syncthreads();

#pragma unroll 5
        for (int k = 0; k < 50; k++) {
            float4 a4 = *(const float4*)(As + k * 64 + r0);
            ulonglong2 bv = *(const ulonglong2*)(Bs + k * 64 + c0);
            ull a0 = pack2(a4.x, a4.x);
            ull a1 = pack2(a4.y, a4.y);
            ull a2 = pack2(a4.z, a4.z);
            ull a3 = pack2(a4.w, a4.w);
            fma2(acc[0][0], a0, bv.x); fma2(acc[0][1], a0, bv.y);
            fma2(acc[1][0], a1, bv.x); fma2(acc[1][1], a1, bv.y);
            fma2(acc[2][0], a2, bv.x); fma2(acc[2][1], a2, bv.y);
            fma2(acc[3][0], a3, bv.x); fma2(acc[3][1], a3, bv.y);
        }
        __syncthreads();
    }

    float bias[4];
#pragma unroll
    for (int p = 0; p < 4; p++) {
        int col = n0 + c0 + p;
        float bv = 0.f;
        if (col < 400)      bv = b[col];
        else if (col < 500) bv = b_t[col - 400];
        else if (col < 600) bv = b_s[col - 500];
        bias[p] = bv;
    }
    const int colg = n0 + c0;
#pragma unroll
    for (int r = 0; r < 4; r++) {
        int row = m0 + r0 + r;
        if (row >= LOCN || colg >= 600) continue;
        float v0, v1, v2, v3;
        unpack2(acc[r][0], v0, v1);
        unpack2(acc[r][1], v2, v3);
        __half2 h01 = __floats2half2_rn(v0 + bias[0], v1 + bias[1]);
        __half2 h23 = __floats2half2_rn(v2 + bias[2], v3 + bias[3]);
        uint2 st;
        st.x = *reinterpret_cast<unsigned*>(&h01);
        st.y = *reinterpret_cast<unsigned*>(&h23);
        *reinterpret_cast<uint2*>(&g_Gloc[(size_t)row * 600 + colg]) = st;
    }
}

// =======================================================================
// Kernel B: P_t = emb_t @ W_tt ; P_s = emb_s @ W_ss  (fp32, tiny)
// =======================================================================
__global__ void kernB(const float* __restrict__ emb_t, const float* __restrict__ W_tt,
                      const float* __restrict__ emb_s, const float* __restrict__ W_ss)
{
    int i = blockIdx.x * blockDim.x + threadIdx.x;
    if (i >= 92 * 100 * 2) return;
    int which = i / 9200;
    int r = i % 9200;
    int s = r / 100, j = r % 100;
    const float* e = which ? emb_s : emb_t;
    const float* W = which ? W_ss : W_tt;
    float acc = 0.f;
#pragma unroll
    for (int d = 0; d < 12; d++) acc += e[s * 12 + d] * W[d * 100 + j];
    (which ? g_Ps : g_Pt)[s * 100 + j] = acc;
}

// =======================================================================
// Kernel C: copy 400 fp16 preacts + compute tsg -> fp16 record [512]
// =======================================================================
__global__ void kernC(const int* __restrict__ traj,
                      const int* __restrict__ tu, const int* __restrict__ tl,
                      const int* __restrict__ tu_slot, const int* __restrict__ tl_slot,
                      const int* __restrict__ su, const int* __restrict__ sl,
                      const int* __restrict__ su_slot, const int* __restrict__ sl_slot)
{
    const int w = threadIdx.x >> 5, lane = threadIdx.x & 31;
    const int token = blockIdx.x * 8 + w;
    const int bb = token >> 8, t = token & 255;

    const int idx = traj[token];
    const __half* gh = g_Gloc + (size_t)idx * 600;
    __half* sh = g_scr + ((size_t)t * BATCH + bb) * RECW;

    {
        const uint4* gv = (const uint4*)gh;
        uint4* ov = (uint4*)sh;
        for (int q = lane; q < 50; q += 32) ov[q] = gv[q];
    }

    if (lane < 25) {
        const float ut = (float)tu_slot[token], lt = (float)tl_slot[token];
        const float us = (float)su_slot[token], ls = (float)sl_slot[token];
        const float rdt = 1.f / fmaxf(ut + lt, 1.f);
        const float rds = 1.f / fmaxf(us + ls, 1.f);
        const float* Ptl = g_Pt + tl[token] * 100;
        const float* Ptu = g_Pt + tu[token] * 100;
        const float* Psl = g_Ps + sl[token] * 100;
        const float* Psu = g_Ps + su[token] * 100;

        const int j0 = lane * 4;
        float ts[4];
#pragma unroll
        for (int k = 0; k < 4; k++) {
            int j = j0 + k;
            float pt = __half2float(gh[400 + j]) + (ut * Ptl[j] + lt * Ptu[j]) * rdt;
            float ps = __half2float(gh[500 + j]) + (us * Psl[j] + ls * Psu[j]) * rds;
            ts[k] = sigf(pt) * sigf(ps);
        }
        __half2 h01 = __floats2half2_rn(ts[0], ts[1]);
        __half2 h23 = __floats2half2_rn(ts[2], ts[3]);
        uint2 st;
        st.x = *reinterpret_cast<unsigned*>(&h01);
        st.y = *reinterpret_cast<unsigned*>(&h23);
        reinterpret_cast<uint2*>(sh + 400)[lane] = st;
    }
}

// =======================================================================
// Kernel D v9: v6/v8 structure + 2-row software pipelining + t-unroll 2.
// =======================================================================
__device__ __forceinline__ float rscatter(ull aA, ull aB, int q) {
    float xl, xh, sA, sB;
    unpack2(aA, xl, xh); sA = xl + xh;
    unpack2(aB, xl, xh); sB = xl + xh;
    float tsend = (q & 2) ? sA : sB;
    float trecv = __shfl_xor_sync(0xffffffffu, tsend, 2);
    float v = ((q & 2) ? sB : sA) + trecv;
    v += __shfl_xor_sync(0xffffffffu, v, 1);
    return v;
}

__global__ void __launch_bounds__(800, 1)
kernD(const float* __restrict__ W_hh, float* __restrict__ out)
{
    __shared__ __align__(16) float  hbuf[2][ROWS_PER_CTA][HSTRIDE];
    __shared__ __align__(16) float  acts[ROWS_PER_CTA][400];
    __shared__ __align__(16) __half sscr[2][ROWS_PER_CTA * RECW];
    __shared__ __align__(8)  ull    smbar[2];

    const int tid = threadIdx.x;
    const int p = tid >> 2, q = tid & 3;
    const int row0 = blockIdx.x * ROWS_PER_CTA;

    const int mycol = p + ((q & 2) ? 200 : 0);
    const int mygate = mycol / 100;
    const float ascale = (mygate == 2) ? 2.f : 1.f;
    const float aA     = (mygate == 2) ? 2.f : 1.f;
    const float aB     = (mygate == 2) ? -1.f : 0.f;
    const bool doST = ((q & 1) == 0);

    const int r_2 = tid / 100, j_2 = tid % 100;
    const bool p2act = (tid < 700);
    const int hslot_2 = 28 * (j_2 / 25) + (j_2 % 25);
    const bool p2out = (row0 + r_2 < BATCH);

    // ---- weights ----
    ull wA[14], wB[14];
#pragma unroll
    for (int m = 0; m < 14; m++) {
        int i0 = 2 * m, i1 = 2 * m + 1;
        float a0 = 0.f, a1 = 0.f, b0 = 0.f, b1 = 0.f;
        if (i0 < 25) {
            int k = 25 * q + i0;
            a0 = W_hh[k * 400 + p];
            b0 = W_hh[k * 400 + p + 200];
        }
        if (i1 < 25) {
            int k = 25 * q + i1;
            a1 = W_hh[k * 400 + p];
            b1 = W_hh[k * 400 + p + 200];
        }
        wA[m] = pack2(a0, a1);
        wB[m] = pack2(b0, b1);
    }

    // ---- init smem ----
    {
        float* pp = &hbuf[0][0][0];
        for (int i = tid; i < 2 * ROWS_PER_CTA * HSTRIDE; i += 800) pp[i] = 0.f;
    }
    uint32_t mb0 = smem_u32(&smbar[0]);
    uint32_t mb1 = smem_u32(&smbar[1]);
    uint32_t sc0 = smem_u32(&sscr[0][0]);
    uint32_t sc1 = smem_u32(&sscr[1][0]);
    if (tid == 0) { mbar_init(mb0, 1); mbar_init(mb1, 1); }
    __syncthreads();

    const __half* scr_base = g_scr + (size_t)row0 * RECW;
    if (tid == 0) {
        mbar_expect_tx(mb0, SCR_BYTES);
        bulk_g2s(sc0, scr_base, SCR_BYTES, mb0);
        mbar_expect_tx(mb1, SCR_BYTES);
        bulk_g2s(sc1, scr_base + (size_t)BATCH * RECW, SCR_BYTES, mb1);
    }

    // loop-invariant per-buf pointers
    const float* hq0 = &hbuf[0][0][0] + q * 28;        // phase-1 h base, buf 0
    const float* hq1 = &hbuf[1][0][0] + q * 28;
    const __half* rec0 = &sscr[0][0] + mycol;          // phase-1 preact base
    const __half* rec1 = &sscr[1][0] + mycol;
    const __half* tsg0 = &sscr[0][0] + r_2 * RECW + 400 + j_2;
    const __half* tsg1 = &sscr[1][0] + r_2 * RECW + 400 + j_2;
    const float*  ap2  = &acts[r_2][j_2];              // phase-2 acts base
    float* hn0 = &hbuf[0][0][0] + r_2 * HSTRIDE + hslot_2;  // phase-2 h store (into buf^1)
    float* hn1 = &hbuf[1][0][0] + r_2 * HSTRIDE + hslot_2;
    float* actw = &acts[0][mycol];
    float* outp = out + (row0 + r_2) * 100 + j_2;

    float creg = 0.f;

#define ROWSUM2(R0, R1, HQ, REC, V0, V1)                                    \
    float V0, V1;                                                           \
    {                                                                       \
        float pre0 = __half2float(REC[(R0) * RECW]);                        \
        float pre1 = __half2float(REC[(R1) * RECW]);                        \
        const ulonglong2* h20 = (const ulonglong2*)(HQ + (R0) * HSTRIDE);   \
        const ulonglong2* h21 = (const ulonglong2*)(HQ + (R1) * HSTRIDE);   \
        ull aA0 = 0, aB0 = 0, aA1 = 0, aB1 = 0;                             \
        _Pragma("unroll")                                                   \
        for (int m = 0; m < 7; m++) {                                       \
            ulonglong2 hv0 = h20[m];                                        \
            ulonglong2 hv1 = h21[m];                                        \
            fma2(aA0, hv0.x, wA[2 * m]);   fma2(aB0, hv0.x, wB[2 * m]);     \
            fma2(aA0, hv0.y, wA[2 * m + 1]); fma2(aB0, hv0.y, wB[2 * m + 1]); \
            fma2(aA1, hv1.x, wA[2 * m]);   fma2(aB1, hv1.x, wB[2 * m]);     \
            fma2(aA1, hv1.y, wA[2 * m + 1]); fma2(aB1, hv1.y, wB[2 * m + 1]); \
        }                                                                   \
        V0 = rscatter(aA0, aB0, q) + pre0;                                  \
        V1 = rscatter(aA1, aB1, q) + pre1;                                  \
    }

#define ROWSUM1(R0, HQ, REC, V0)                                            \
    float V0;                                                               \
    {                                                                       \
        float pre0 = __half2float(REC[(R0) * RECW]);                        \
        const ulonglong2* h20 = (const ulonglong2*)(HQ + (R0) * HSTRIDE);   \
        ull aA0 = 0, aB0 = 0;                                               \
        _Pragma("unroll")                                                   \
        for (int m = 0; m < 7; m++) {                                       \
            ulonglong2 hv0 = h20[m];                                        \
            fma2(aA0, hv0.x, wA[2 * m]);   fma2(aB0, hv0.x, wB[2 * m]);     \
            fma2(aA0, hv0.y, wA[2 * m + 1]); fma2(aB0, hv0.y, wB[2 * m + 1]); \
        }                                                                   \
        V0 = rscatter(aA0, aB0, q) + pre0;                                  \
    }

#define ACT2(R0, R1, V0, V1)                                                \
    {                                                                       \
        float s0 = 1.f / (1.f + __expf(-ascale * (V0)));                    \
        float s1 = 1.f / (1.f + __expf(-ascale * (V1)));                    \
        float a0 = fmaf(s0, aA, aB);                                        \
        float a1 = fmaf(s1, aA, aB);                                        \
        if (doST) { actw[(R0) * 400] = a0; actw[(R1) * 400] = a1; }         \
    }

#define ACT1(R0, V0)                                                        \
    {                                                                       \
        float s0 = 1.f / (1.f + __expf(-ascale * (V0)));                    \
        float a0 = fmaf(s0, aA, aB);                                        \
        if (doST) actw[(R0) * 400] = a0;                                    \
    }

#define STEP(BUF, T, PAR, HQ, REC, TSGP, HNP)                               \
    {                                                                       \
        mbar_wait((BUF) ? mb1 : mb0, (PAR));                                \
        { ROWSUM2(0, 1, HQ, REC, v0, v1) ACT2(0, 1, v0, v1) }               \
        { ROWSUM2(2, 3, HQ, REC, v2, v3) ACT2(2, 3, v2, v3) }               \
        { ROWSUM2(4, 5, HQ, REC, v4, v5) ACT2(4, 5, v4, v5) }               \
        { ROWSUM1(6, HQ, REC, v6) ACT1(6, v6) }                             \
        __syncthreads();                                                    \
        if (p2act) {                                                        \
            float gi = ap2[0], gf = ap2[100], gg = ap2[200], go = ap2[300]; \
            float tsg = __half2float(*(TSGP));                              \
            float cN = gf * creg + gi * tsg * gg;                           \
            creg = cN;                                                      \
            float h = go * tanh_fast(cN);                                   \
            *(HNP) = h;                                                     \
            if ((T) == TSTEPS - 1 && p2out) *outp = h;                      \
        }                                                                   \
        __syncthreads();                                                    \
        if ((T) + 2 < TSTEPS && tid == 0) {                                 \
            uint32_t mb = (BUF) ? mb1 : mb0;                                \
            mbar_expect_tx(mb, SCR_BYTES);                                  \
            bulk_g2s((BUF) ? sc1 : sc0,                                     \
                     scr_base + (size_t)((T) + 2) * BATCH * RECW, SCR_BYTES, mb); \
        }                                                                   \
    }

#pragma unroll 1
    for (int s = 0; s < TSTEPS / 2; s++) {
        const int par = s & 1;
        const int t0 = 2 * s;
        STEP(0, t0, par, hq0, rec0, tsg0, hn1)      // buf0: h in buf0, write h to buf1
        STEP(1, t0 + 1, par, hq1, rec1, tsg1, hn0)  // buf1: h in buf1, write h to buf0
    }
#undef STEP
#undef ACT1
#undef ACT2
#undef ROWSUM1
#undef ROWSUM2
}

// =======================================================================
// launch
// =======================================================================
extern "C" void kernel_launch(void* const* d_in, const int* in_sizes, int n_in,
                              void* d_out, int out_size)
{
    (void)in_sizes; (void)n_in; (void)out_size;
    const int*   traj    = (const int*)d_in[0];
    const int*   tu      = (const int*)d_in[3];
    const int*   tl      = (const int*)d_in[4];
    const int*   tu_s    = (const int*)d_in[5];
    const int*   tl_s    = (const int*)d_in[6];
    const int*   su      = (const int*)d_in[7];
    const int*   sl      = (const int*)d_in[8];
    const int*   su_s    = (const int*)d_in[9];
    const int*   sl_s    = (const int*)d_in[10];
    const float* emb_loc = (const float*)d_in[11];
    const float* emb_t   = (const float*)d_in[12];
    const float* emb_s   = (const float*)d_in[13];
    const float* W_ih    = (const float*)d_in[14];
    const float* W_hh    = (const float*)d_in[15];
    const float* b       = (const float*)d_in[16];
    const float* W_xt    = (const float*)d_in[17];
    const float* W_tt    = (const float*)d_in[18];
    const float* b_t     = (const float*)d_in[19];
    const float* W_xs    = (const float*)d_in[20];
    const float* W_ss    = (const float*)d_in[21];
    const float* b_s     = (const float*)d_in[22];
    float* out = (float*)d_out;

    dim3 gA((LOCN + 63) / 64, 10);
    kernA<<<gA, 256>>>(emb_loc, W_ih, W_xt, W_xs, b, b_t, b_s);

    kernB<<<(92 * 100 * 2 + 255) / 256, 256>>>(emb_t, W_tt, emb_s, W_ss);

    kernC<<<(BATCH * TSTEPS) / 8, 256>>>(traj, tu, tl, tu_s, tl_s, su, sl, su_s, sl_s);

    kernD<<<NCTA, 800>>>(W_hh, out);
}

// round 10
// speedup vs baseline: 1.2794x; 1.0615x over previous
#include <cuda_runtime.h>
#include <cuda_fp16.h>
#include <cstdint>

typedef unsigned long long ull;

#define LOCN   40001
#define BATCH  1024
#define TSTEPS 256

#define ROWS_PER_CTA 7
#define NCTA ((BATCH + ROWS_PER_CTA - 1) / ROWS_PER_CTA)   // 147
#define HSTRIDE 112                          // 4 quarters of 28 floats; real k=25q+i at 28q+i
#define RECW 512                             // scratch record width in halfs (1024 B)
#define SCR_BYTES (ROWS_PER_CTA * RECW * 2)  // 7168, multiple of 16

// ---------------- device scratch ----------------
__device__ __half g_Gloc[(size_t)LOCN * 600];                  // fp16: 48 MB
__device__ float  g_Pt[92 * 100];
__device__ float  g_Ps[92 * 100];
__device__ __half g_scr[(size_t)TSTEPS * BATCH * RECW + 8192]; // fp16 records: 268 MB

// ---------------- helpers ----------------
__device__ __forceinline__ float sigf(float x) { return 1.f / (1.f + __expf(-x)); }
__device__ __forceinline__ float tanh_fast(float x) { return 1.f - 2.f / (1.f + __expf(2.f * x)); }

__device__ __forceinline__ ull pack2(float lo, float hi) {
    ull r; asm("mov.b64 %0, {%1, %2};" : "=l"(r) : "f"(lo), "f"(hi)); return r;
}
__device__ __forceinline__ void unpack2(ull v, float& lo, float& hi) {
    asm("mov.b64 {%0, %1}, %2;" : "=f"(lo), "=f"(hi) : "l"(v));
}
__device__ __forceinline__ void fma2(ull& acc, ull a, ull b) {
    asm("fma.rn.f32x2 %0, %1, %2, %0;" : "+l"(acc) : "l"(a), "l"(b));
}
__device__ __forceinline__ uint32_t smem_u32(const void* p) {
    uint32_t a;
    asm("{ .reg .u64 t; cvta.to.shared.u64 t, %1; cvt.u32.u64 %0, t; }" : "=r"(a) : "l"(p));
    return a;
}
__device__ __forceinline__ void mbar_init(uint32_t mbar, uint32_t cnt) {
    asm volatile("mbarrier.init.shared.b64 [%0], %1;" :: "r"(mbar), "r"(cnt) : "memory");
}
__device__ __forceinline__ void mbar_expect_tx(uint32_t mbar, uint32_t bytes) {
    asm volatile("mbarrier.arrive.expect_tx.shared.b64 _, [%0], %1;" :: "r"(mbar), "r"(bytes) : "memory");
}
__device__ __forceinline__ void bulk_g2s(uint32_t dst, const void* src, uint32_t bytes, uint32_t mbar) {
    asm volatile("cp.async.bulk.shared::cta.global.mbarrier::complete_tx::bytes [%0], [%1], %2, [%3];"
                 :: "r"(dst), "l"(src), "r"(bytes), "r"(mbar) : "memory");
}
__device__ __forceinline__ void mbar_wait(uint32_t mbar, uint32_t parity) {
    uint32_t done;
    asm volatile("{\n\t.reg .pred p;\n\t"
                 "mbarrier.try_wait.parity.acquire.cta.shared::cta.b64 p, [%1], %2;\n\t"
                 "selp.b32 %0, 1, 0, p;\n\t}"
                 : "=r"(done) : "r"(mbar), "r"(parity) : "memory");
    if (!done) {
        asm volatile("{\n\t.reg .pred P1;\n\t"
                     "WL_%=:\n\t"
                     "mbarrier.try_wait.parity.acquire.cta.shared::cta.b64 P1, [%0], %1, 0x989680;\n\t"
                     "@P1 bra.uni WD_%=;\n\t"
                     "bra.uni WL_%=;\n\t"
                     "WD_%=:\n\t}"
                     :: "r"(mbar), "r"(parity) : "memory");
    }
}

// =======================================================================
// Kernel A (tensor-core): Gloc = fp16( emb_loc @ [W_ih|W_xt|W_xs] + bias )
//  mma.sync.m16n8k16 f16*f16+f32. CTA tile 64(M) x 120(N), K=100 pad 112.
//  grid = (5 n-tiles, 626 m-tiles). 128 threads = 4 m-warps of 16 rows.
//  smem: A[64][120] halfs (stride 120 -> conflict-free ldmatrix),
//        B[112][120] halfs. Per warp: 7 k-chunks x (1 ldm.x4 A +
//        7 ldm.x4.trans + 1 ldm.x2.trans B + 15 mma).
// =======================================================================
#define KA_AS 120   // smem row stride (halfs) for both tiles

__global__ void __launch_bounds__(128)
kernA(const float* __restrict__ emb_loc,
      const float* __restrict__ W_ih,
      const float* __restrict__ W_xt,
      const float* __restrict__ W_xs,
      const float* __restrict__ b,
      const float* __restrict__ b_t,
      const float* __restrict__ b_s)
{
    __shared__ __align__(16) __half As[64 * KA_AS];
    __shared__ __align__(16) __half Bs[112 * KA_AS];

    const int tid = threadIdx.x;
    const int warp = tid >> 5, lane = tid & 31;
    const int n0 = blockIdx.x * 120;
    const int m0 = blockIdx.y * 64;

    // ---- load A tile (fp32 -> fp16), zero-padded ----
    for (int i = tid; i < 64 * 112; i += 128) {
        int r = i / 112, k = i % 112;
        int row = m0 + r;
        float v = (row < LOCN && k < 100) ? emb_loc[(size_t)row * 100 + k] : 0.f;
        As[r * KA_AS + k] = __float2half(v);
    }
    // ---- load B tile (fp32 -> fp16), zero-padded ----
    for (int i = tid; i < 112 * 120; i += 128) {
        int k = i / 120, c = i % 120;
        int col = n0 + c;
        float v = 0.f;
        if (k < 100) {
            if (col < 400)      v = W_ih[k * 400 + col];
            else if (col < 500) v = W_xt[k * 100 + (col - 400)];
            else                v = W_xs[k * 100 + (col - 500)];
        }
        Bs[k * KA_AS + c] = __float2half(v);
    }
    __syncthreads();

    const int g8 = lane >> 3, lr = lane & 7;

    float acc[15][4];
#pragma unroll
    for (int i = 0; i < 15; i++) { acc[i][0] = acc[i][1] = acc[i][2] = acc[i][3] = 0.f; }

    // A ldmatrix address (per lane), reused each k-chunk with offset
    const int a_row = warp * 16 + (g8 & 1) * 8 + lr;
    const int a_kof = (g8 >> 1) * 8;
    const uint32_t a_base = smem_u32(&As[a_row * KA_AS + a_kof]);
    // B ldmatrix.x4.trans address parts
    const int b_kof = (g8 & 1) * 8 + lr;
    const int b_nof = (g8 >> 1) * 8;
    const uint32_t b_base = smem_u32(&Bs[b_kof * KA_AS + b_nof]);
    // B ldmatrix.x2.trans (last 8 cols): lanes 0-15 meaningful, mirror for 16-31
    const int b2_kof = ((lane >> 3) & 1) * 8 + lr;
    const uint32_t b2_base = smem_u32(&Bs[b2_kof * KA_AS + 112]);

#pragma unroll
    for (int kc = 0; kc < 7; kc++) {
        uint32_t a0, a1, a2, a3;
        asm volatile("ldmatrix.sync.aligned.m8n8.x4.shared.b16 {%0,%1,%2,%3}, [%4];"
                     : "=r"(a0), "=r"(a1), "=r"(a2), "=r"(a3)
                     : "r"(a_base + kc * 16 * 2));
#pragma unroll
        for (int pr = 0; pr < 7; pr++) {
            uint32_t b0, b1, b2, b3;
            asm volatile("ldmatrix.sync.aligned.m8n8.x4.trans.shared.b16 {%0,%1,%2,%3}, [%4];"
                         : "=r"(b0), "=r"(b1), "=r"(b2), "=r"(b3)
                         : "r"(b_base + (kc * 16 * KA_AS + pr * 16) * 2));
            asm volatile("mma.sync.aligned.m16n8k16.row.col.f32.f16.f16.f32 "
                         "{%0,%1,%2,%3}, {%4,%5,%6,%7}, {%8,%9}, {%0,%1,%2,%3};"
                         : "+f"(acc[2 * pr][0]), "+f"(acc[2 * pr][1]),
                           "+f"(acc[2 * pr][2]), "+f"(acc[2 * pr][3])
                         : "r"(a0), "r"(a1), "r"(a2), "r"(a3), "r"(b0), "r"(b1));
            asm volatile("mma.sync.aligned.m16n8k16.row.col.f32.f16.f16.f32 "
                         "{%0,%1,%2,%3}, {%4,%5,%6,%7}, {%8,%9}, {%0,%1,%2,%3};"
                         : "+f"(acc[2 * pr + 1][0]), "+f"(acc[2 * pr + 1][1]),
                           "+f"(acc[2 * pr + 1][2]), "+f"(acc[2 * pr + 1][3])
                         : "r"(a0), "r"(a1), "r"(a2), "r"(a3), "r"(b2), "r"(b3));
        }
        {   // last n-tile (cols 112..119)
            uint32_t b0, b1;
            asm volatile("ldmatrix.sync.aligned.m8n8.x2.trans.shared.b16 {%0,%1}, [%2];"
                         : "=r"(b0), "=r"(b1)
                         : "r"(b2_base + kc * 16 * KA_AS * 2));
            asm volatile("mma.sync.aligned.m16n8k16.row.col.f32.f16.f16.f32 "
                         "{%0,%1,%2,%3}, {%4,%5,%6,%7}, {%8,%9}, {%0,%1,%2,%3};"
                         : "+f"(acc[14][0]), "+f"(acc[14][1]),
                           "+f"(acc[14][2]), "+f"(acc[14][3])
                         : "r"(a0), "r"(a1), "r"(a2), "r"(a3), "r"(b0), "r"(b1));
        }
    }

    // ---- epilogue: bias + fp16 pack + store ----
    const int row_lo = m0 + warp * 16 + (lane >> 2);
    const int row_hi = row_lo + 8;
#pragma unroll
    for (int nt = 0; nt < 15; nt++) {
        int col = n0 + nt * 8 + (lane & 3) * 2;
        float bias0, bias1;
        if (col < 400)      { bias0 = b[col];        bias1 = b[col + 1]; }
        else if (col < 500) { bias0 = b_t[col - 400]; bias1 = b_t[col - 399]; }
        else                { bias0 = b_s[col - 500]; bias1 = b_s[col - 499]; }
        __half2 lo = __floats2half2_rn(acc[nt][0] + bias0, acc[nt][1] + bias1);
        __half2 hi = __floats2half2_rn(acc[nt][2] + bias0, acc[nt][3] + bias1);
        if (row_lo < LOCN)
            *reinterpret_cast<unsigned*>(&g_Gloc[(size_t)row_lo * 600 + col]) =
                *reinterpret_cast<unsigned*>(&lo);
        if (row_hi < LOCN)
            *reinterpret_cast<unsigned*>(&g_Gloc[(size_t)row_hi * 600 + col]) =
                *reinterpret_cast<unsigned*>(&hi);
    }
}

// =======================================================================
// Kernel B: P_t = emb_t @ W_tt ; P_s = emb_s @ W_ss  (fp32, tiny)
// =======================================================================
__global__ void kernB(const float* __restrict__ emb_t, const float* __restrict__ W_tt,
                      const float* __restrict__ emb_s, const float* __restrict__ W_ss)
{
    int i = blockIdx.x * blockDim.x + threadIdx.x;
    if (i >= 92 * 100 * 2) return;
    int which = i / 9200;
    int r = i % 9200;
    int s = r / 100, j = r % 100;
    const float* e = which ? emb_s : emb_t;
    const float* W = which ? W_ss : W_tt;
    float acc = 0.f;
#pragma unroll
    for (int d = 0; d < 12; d++) acc += e[s * 12 + d] * W[d * 100 + j];
    (which ? g_Ps : g_Pt)[s * 100 + j] = acc;
}

// =======================================================================
// Kernel C: copy 400 fp16 preacts + compute tsg -> fp16 record [512]
// =======================================================================
__global__ void kernC(const int* __restrict__ traj,
                      const int* __restrict__ tu, const int* __restrict__ tl,
                      const int* __restrict__ tu_slot, const int* __restrict__ tl_slot,
                      const int* __restrict__ su, const int* __restrict__ sl,
                      const int* __restrict__ su_slot, const int* __restrict__ sl_slot)
{
    const int w = threadIdx.x >> 5, lane = threadIdx.x & 31;
    const int token = blockIdx.x * 8 + w;
    const int bb = token >> 8, t = token & 255;

    const int idx = traj[token];
    const __half* gh = g_Gloc + (size_t)idx * 600;
    __half* sh = g_scr + ((size_t)t * BATCH + bb) * RECW;

    {
        const uint4* gv = (const uint4*)gh;
        uint4* ov = (uint4*)sh;
        for (int q = lane; q < 50; q += 32) ov[q] = gv[q];
    }

    if (lane < 25) {
        const float ut = (float)tu_slot[token], lt = (float)tl_slot[token];
        const float us = (float)su_slot[token], ls = (float)sl_slot[token];
        const float rdt = 1.f / fmaxf(ut + lt, 1.f);
        const float rds = 1.f / fmaxf(us + ls, 1.f);
        const float* Ptl = g_Pt + tl[token] * 100;
        const float* Ptu = g_Pt + tu[token] * 100;
        const float* Psl = g_Ps + sl[token] * 100;
        const float* Psu = g_Ps + su[token] * 100;

        const int j0 = lane * 4;
        float ts[4];
#pragma unroll
        for (int k = 0; k < 4; k++) {
            int j = j0 + k;
            float pt = __half2float(gh[400 + j]) + (ut * Ptl[j] + lt * Ptu[j]) * rdt;
            float ps = __half2float(gh[500 + j]) + (us * Psl[j] + ls * Psu[j]) * rds;
            ts[k] = sigf(pt) * sigf(ps);
        }
        __half2 h01 = __floats2half2_rn(ts[0], ts[1]);
        __half2 h23 = __floats2half2_rn(ts[2], ts[3]);
        uint2 st;
        st.x = *reinterpret_cast<unsigned*>(&h01);
        st.y = *reinterpret_cast<unsigned*>(&h23);
        reinterpret_cast<uint2*>(sh + 400)[lane] = st;
    }
}

// =======================================================================
// Kernel D v9 (unchanged): column-pair + 4-way k split, 2-row pipelining,
// t-unroll 2, fp16 scratch staged via cp.async.bulk.
// =======================================================================
__device__ __forceinline__ float rscatter(ull aA, ull aB, int q) {
    float xl, xh, sA, sB;
    unpack2(aA, xl, xh); sA = xl + xh;
    unpack2(aB, xl, xh); sB = xl + xh;
    float tsend = (q & 2) ? sA : sB;
    float trecv = __shfl_xor_sync(0xffffffffu, tsend, 2);
    float v = ((q & 2) ? sB : sA) + trecv;
    v += __shfl_xor_sync(0xffffffffu, v, 1);
    return v;
}

__global__ void __launch_bounds__(800, 1)
kernD(const float* __restrict__ W_hh, float* __restrict__ out)
{
    __shared__ __align__(16) float  hbuf[2][ROWS_PER_CTA][HSTRIDE];
    __shared__ __align__(16) float  acts[ROWS_PER_CTA][400];
    __shared__ __align__(16) __half sscr[2][ROWS_PER_CTA * RECW];
    __shared__ __align__(8)  ull    smbar[2];

    const int tid = threadIdx.x;
    const int p = tid >> 2, q = tid & 3;
    const int row0 = blockIdx.x * ROWS_PER_CTA;

    const int mycol = p + ((q & 2) ? 200 : 0);
    const int mygate = mycol / 100;
    const float ascale = (mygate == 2) ? 2.f : 1.f;
    const float aA     = (mygate == 2) ? 2.f : 1.f;
    const float aB     = (mygate == 2) ? -1.f : 0.f;
    const bool doST = ((q & 1) == 0);

    const int r_2 = tid / 100, j_2 = tid % 100;
    const bool p2act = (tid < 700);
    const int hslot_2 = 28 * (j_2 / 25) + (j_2 % 25);
    const bool p2out = (row0 + r_2 < BATCH);

    // ---- weights ----
    ull wA[14], wB[14];
#pragma unroll
    for (int m = 0; m < 14; m++) {
        int i0 = 2 * m, i1 = 2 * m + 1;
        float a0 = 0.f, a1 = 0.f, b0 = 0.f, b1 = 0.f;
        if (i0 < 25) {
            int k = 25 * q + i0;
            a0 = W_hh[k * 400 + p];
            b0 = W_hh[k * 400 + p + 200];
        }
        if (i1 < 25) {
            int k = 25 * q + i1;
            a1 = W_hh[k * 400 + p];
            b1 = W_hh[k * 400 + p + 200];
        }
        wA[m] = pack2(a0, a1);
        wB[m] = pack2(b0, b1);
    }

    // ---- init smem ----
    {
        float* pp = &hbuf[0][0][0];
        for (int i = tid; i < 2 * ROWS_PER_CTA * HSTRIDE; i += 800) pp[i] = 0.f;
    }
    uint32_t mb0 = smem_u32(&smbar[0]);
    uint32_t mb1 = smem_u32(&smbar[1]);
    uint32_t sc0 = smem_u32(&sscr[0][0]);
    uint32_t sc1 = smem_u32(&sscr[1][0]);
    if (tid == 0) { mbar_init(mb0, 1); mbar_init(mb1, 1); }
    __syncthreads();

    const __half* scr_base = g_scr + (size_t)row0 * RECW;
    if (tid == 0) {
        mbar_expect_tx(mb0, SCR_BYTES);
        bulk_g2s(sc0, scr_base, SCR_BYTES, mb0);
        mbar_expect_tx(mb1, SCR_BYTES);
        bulk_g2s(sc1, scr_base + (size_t)BATCH * RECW, SCR_BYTES, mb1);
    }

    // loop-invariant per-buf pointers
    const float* hq0 = &hbuf[0][0][0] + q * 28;
    const float* hq1 = &hbuf[1][0][0] + q * 28;
    const __half* rec0 = &sscr[0][0] + mycol;
    const __half* rec1 = &sscr[1][0] + mycol;
    const __half* tsg0 = &sscr[0][0] + r_2 * RECW + 400 + j_2;
    const __half* tsg1 = &sscr[1][0] + r_2 * RECW + 400 + j_2;
    const float*  ap2  = &acts[r_2][j_2];
    float* hn0 = &hbuf[0][0][0] + r_2 * HSTRIDE + hslot_2;
    float* hn1 = &hbuf[1][0][0] + r_2 * HSTRIDE + hslot_2;
    float* actw = &acts[0][mycol];
    float* outp = out + (row0 + r_2) * 100 + j_2;

    float creg = 0.f;

#define ROWSUM2(R0, R1, HQ, REC, V0, V1)                                    \
    float V0, V1;                                                           \
    {                                                                       \
        float pre0 = __half2float(REC[(R0) * RECW]);                        \
        float pre1 = __half2float(REC[(R1) * RECW]);                        \
        const ulonglong2* h20 = (const ulonglong2*)(HQ + (R0) * HSTRIDE);   \
        const ulonglong2* h21 = (const ulonglong2*)(HQ + (R1) * HSTRIDE);   \
        ull aA0 = 0, aB0 = 0, aA1 = 0, aB1 = 0;                             \
        _Pragma("unroll")                                                   \
        for (int m = 0; m < 7; m++) {                                       \
            ulonglong2 hv0 = h20[m];                                        \
            ulonglong2 hv1 = h21[m];                                        \
            fma2(aA0, hv0.x, wA[2 * m]);   fma2(aB0, hv0.x, wB[2 * m]);     \
            fma2(aA0, hv0.y, wA[2 * m + 1]); fma2(aB0, hv0.y, wB[2 * m + 1]); \
            fma2(aA1, hv1.x, wA[2 * m]);   fma2(aB1, hv1.x, wB[2 * m]);     \
            fma2(aA1, hv1.y, wA[2 * m + 1]); fma2(aB1, hv1.y, wB[2 * m + 1]); \
        }                                                                   \
        V0 = rscatter(aA0, aB0, q) + pre0;                                  \
        V1 = rscatter(aA1, aB1, q) + pre1;                                  \
    }

#define ROWSUM1(R0, HQ, REC, V0)                                            \
    float V0;                                                               \
    {                                                                       \
        float pre0 = __half2float(REC[(R0) * RECW]);                        \
        const ulonglong2* h20 = (const ulonglong2*)(HQ + (R0) * HSTRIDE);   \
        ull aA0 = 0, aB0 = 0;                                               \
        _Pragma("unroll")                                                   \
        for (int m = 0; m < 7; m++) {                                       \
            ulonglong2 hv0 = h20[m];                                        \
            fma2(aA0, hv0.x, wA[2 * m]);   fma2(aB0, hv0.x, wB[2 * m]);     \
            fma2(aA0, hv0.y, wA[2 * m + 1]); fma2(aB0, hv0.y, wB[2 * m + 1]); \
        }                                                                   \
        V0 = rscatter(aA0, aB0, q) + pre0;                                  \
    }

#define ACT2(R0, R1, V0, V1)                                                \
    {                                                                       \
        float s0 = 1.f / (1.f + __expf(-ascale * (V0)));                    \
        float s1 = 1.f / (1.f + __expf(-ascale * (V1)));                    \
        float a0 = fmaf(s0, aA, aB);                                        \
        float a1 = fmaf(s1, aA, aB);                                        \
        if (doST) { actw[(R0) * 400] = a0; actw[(R1) * 400] = a1; }         \
    }

#define ACT1(R0, V0)                                                        \
    {                                                                       \
        float s0 = 1.f / (1.f + __expf(-ascale * (V0)));                    \
        float a0 = fmaf(s0, aA, aB);                                        \
        if (doST) actw[(R0) * 400] = a0;                                    \
    }

#define STEP(BUF, T, PAR, HQ, REC, TSGP, HNP)                               \
    {                                                                       \
        mbar_wait((BUF) ? mb1 : mb0, (PAR));                                \
        { ROWSUM2(0, 1, HQ, REC, v0, v1) ACT2(0, 1, v0, v1) }               \
        { ROWSUM2(2, 3, HQ, REC, v2, v3) ACT2(2, 3, v2, v3) }               \
        { ROWSUM2(4, 5, HQ, REC, v4, v5) ACT2(4, 5, v4, v5) }               \
        { ROWSUM1(6, HQ, REC, v6) ACT1(6, v6) }                             \
        __syncthreads();                                                    \
        if (p2act) {                                                        \
            float gi = ap2[0], gf = ap2[100], gg = ap2[200], go = ap2[300]; \
            float tsg = __half2float(*(TSGP));                              \
            float cN = gf * creg + gi * tsg * gg;                           \
            creg = cN;                                                      \
            float h = go * tanh_fast(cN);                                   \
            *(HNP) = h;                                                     \
            if ((T) == TSTEPS - 1 && p2out) *outp = h;                      \
        }                                                                   \
        __syncthreads();                                                    \
        if ((T) + 2 < TSTEPS && tid == 0) {                                 \
            uint32_t mb = (BUF) ? mb1 : mb0;                                \
            mbar_expect_tx(mb, SCR_BYTES);                                  \
            bulk_g2s((BUF) ? sc1 : sc0,                                     \
                     scr_base + (size_t)((T) + 2) * BATCH * RECW, SCR_BYTES, mb); \
        }                                                                   \
    }

#pragma unroll 1
    for (int s = 0; s < TSTEPS / 2; s++) {
        const int par = s & 1;
        const int t0 = 2 * s;
        STEP(0, t0, par, hq0, rec0, tsg0, hn1)
        STEP(1, t0 + 1, par, hq1, rec1, tsg1, hn0)
    }
#undef STEP
#undef ACT1
#undef ACT2
#undef ROWSUM1
#undef ROWSUM2
}

// =======================================================================
// launch
// =======================================================================
extern "C" void kernel_launch(void* const* d_in, const int* in_sizes, int n_in,
                              void* d_out, int out_size)
{
    (void)in_sizes; (void)n_in; (void)out_size;
    const int*   traj    = (const int*)d_in[0];
    const int*   tu      = (const int*)d_in[3];
    const int*   tl      = (const int*)d_in[4];
    const int*   tu_s    = (const int*)d_in[5];
    const int*   tl_s    = (const int*)d_in[6];
    const int*   su      = (const int*)d_in[7];
    const int*   sl      = (const int*)d_in[8];
    const int*   su_s    = (const int*)d_in[9];
    const int*   sl_s    = (const int*)d_in[10];
    const float* emb_loc = (const float*)d_in[11];
    const float* emb_t   = (const float*)d_in[12];
    const float* emb_s   = (const float*)d_in[13];
    const float* W_ih    = (const float*)d_in[14];
    const float* W_hh    = (const float*)d_in[15];
    const float* b       = (const float*)d_in[16];
    const float* W_xt    = (const float*)d_in[17];
    const float* W_tt    = (const float*)d_in[18];
    const float* b_t     = (const float*)d_in[19];
    const float* W_xs    = (const float*)d_in[20];
    const float* W_ss    = (const float*)d_in[21];
    const float* b_s     = (const float*)d_in[22];
    float* out = (float*)d_out;

    // A: tensor-core GEMM. grid x = 5 n-tiles (fast, shares A block in L2),
    // y = 626 m-tiles.
    dim3 gA(5, (LOCN + 63) / 64);
    kernA<<<gA, 128>>>(emb_loc, W_ih, W_xt, W_xs, b, b_t, b_s);

    kernB<<<(92 * 100 * 2 + 255) / 256, 256>>>(emb_t, W_tt, emb_s, W_ss);

    kernC<<<(BATCH * TSTEPS) / 8, 256>>>(traj, tu, tl, tu_s, tl_s, su, sl, su_s, sl_s);

    kernD<<<NCTA, 800>>>(W_hh, out);
}

// round 11
// speedup vs baseline: 2.7528x; 2.1515x over previous
#include <cuda_runtime.h>
#include <cuda_fp16.h>
#include <cstdint>

typedef unsigned long long ull;

#define LOCN   40001
#define BATCH  1024
#define TSTEPS 256

#define ROWS_PER_CTA 7
#define NCTA ((BATCH + ROWS_PER_CTA - 1) / ROWS_PER_CTA)   // 147
#define RECW 512                             // scratch record width in halfs (1024 B)
#define SCR_BYTES (ROWS_PER_CTA * RECW * 2)  // 7168, multiple of 16
#define HS2 120                              // fp16 h row stride (240 B -> conflict-free ldmatrix)

// ---------------- device scratch ----------------
__device__ __half g_Gloc[(size_t)LOCN * 600];                  // fp16: 48 MB
__device__ float  g_Pt[92 * 100];
__device__ float  g_Ps[92 * 100];
__device__ __half g_scr[(size_t)TSTEPS * BATCH * RECW + 8192]; // fp16 records: 268 MB

// ---------------- helpers ----------------
__device__ __forceinline__ float sigf(float x) { return 1.f / (1.f + __expf(-x)); }
__device__ __forceinline__ float tanh_fast(float x) { return 1.f - 2.f / (1.f + __expf(2.f * x)); }

__device__ __forceinline__ ull pack2(float lo, float hi) {
    ull r; asm("mov.b64 %0, {%1, %2};" : "=l"(r) : "f"(lo), "f"(hi)); return r;
}
__device__ __forceinline__ void unpack2(ull v, float& lo, float& hi) {
    asm("mov.b64 {%0, %1}, %2;" : "=f"(lo), "=f"(hi) : "l"(v));
}
__device__ __forceinline__ void fma2(ull& acc, ull a, ull b) {
    asm("fma.rn.f32x2 %0, %1, %2, %0;" : "+l"(acc) : "l"(a), "l"(b));
}
__device__ __forceinline__ uint32_t smem_u32(const void* p) {
    uint32_t a;
    asm("{ .reg .u64 t; cvta.to.shared.u64 t, %1; cvt.u32.u64 %0, t; }" : "=r"(a) : "l"(p));
    return a;
}
__device__ __forceinline__ void mbar_init(uint32_t mbar, uint32_t cnt) {
    asm volatile("mbarrier.init.shared.b64 [%0], %1;" :: "r"(mbar), "r"(cnt) : "memory");
}
__device__ __forceinline__ void mbar_expect_tx(uint32_t mbar, uint32_t bytes) {
    asm volatile("mbarrier.arrive.expect_tx.shared.b64 _, [%0], %1;" :: "r"(mbar), "r"(bytes) : "memory");
}
__device__ __forceinline__ void bulk_g2s(uint32_t dst, const void* src, uint32_t bytes, uint32_t mbar) {
    asm volatile("cp.async.bulk.shared::cta.global.mbarrier::complete_tx::bytes [%0], [%1], %2, [%3];"
                 :: "r"(dst), "l"(src), "r"(bytes), "r"(mbar) : "memory");
}
__device__ __forceinline__ void mbar_wait(uint32_t mbar, uint32_t parity) {
    uint32_t done;
    asm volatile("{\n\t.reg .pred p;\n\t"
                 "mbarrier.try_wait.parity.acquire.cta.shared::cta.b64 p, [%1], %2;\n\t"
                 "selp.b32 %0, 1, 0, p;\n\t}"
                 : "=r"(done) : "r"(mbar), "r"(parity) : "memory");
    if (!done) {
        asm volatile("{\n\t.reg .pred P1;\n\t"
                     "WL_%=:\n\t"
                     "mbarrier.try_wait.parity.acquire.cta.shared::cta.b64 P1, [%0], %1, 0x989680;\n\t"
                     "@P1 bra.uni WD_%=;\n\t"
                     "bra.uni WL_%=;\n\t"
                     "WD_%=:\n\t}"
                     :: "r"(mbar), "r"(parity) : "memory");
    }
}

// =======================================================================
// Kernel A (tensor-core): Gloc = fp16( emb_loc @ [W_ih|W_xt|W_xs] + bias )
// (unchanged from R10)
// =======================================================================
#define KA_AS 120

__global__ void __launch_bounds__(128)
kernA(const float* __restrict__ emb_loc,
      const float* __restrict__ W_ih,
      const float* __restrict__ W_xt,
      const float* __restrict__ W_xs,
      const float* __restrict__ b,
      const float* __restrict__ b_t,
      const float* __restrict__ b_s)
{
    __shared__ __align__(16) __half As[64 * KA_AS];
    __shared__ __align__(16) __half Bs[112 * KA_AS];

    const int tid = threadIdx.x;
    const int warp = tid >> 5, lane = tid & 31;
    const int n0 = blockIdx.x * 120;
    const int m0 = blockIdx.y * 64;

    for (int i = tid; i < 64 * 112; i += 128) {
        int r = i / 112, k = i % 112;
        int row = m0 + r;
        float v = (row < LOCN && k < 100) ? emb_loc[(size_t)row * 100 + k] : 0.f;
        As[r * KA_AS + k] = __float2half(v);
    }
    for (int i = tid; i < 112 * 120; i += 128) {
        int k = i / 120, c = i % 120;
        int col = n0 + c;
        float v = 0.f;
        if (k < 100) {
            if (col < 400)      v = W_ih[k * 400 + col];
            else if (col < 500) v = W_xt[k * 100 + (col - 400)];
            else                v = W_xs[k * 100 + (col - 500)];
        }
        Bs[k * KA_AS + c] = __float2half(v);
    }
    __syncthreads();

    const int g8 = lane >> 3, lr = lane & 7;

    float acc[15][4];
#pragma unroll
    for (int i = 0; i < 15; i++) { acc[i][0] = acc[i][1] = acc[i][2] = acc[i][3] = 0.f; }

    const int a_row = warp * 16 + (g8 & 1) * 8 + lr;
    const int a_kof = (g8 >> 1) * 8;
    const uint32_t a_base = smem_u32(&As[a_row * KA_AS + a_kof]);
    const int b_kof = (g8 & 1) * 8 + lr;
    const int b_nof = (g8 >> 1) * 8;
    const uint32_t b_base = smem_u32(&Bs[b_kof * KA_AS + b_nof]);
    const int b2_kof = ((lane >> 3) & 1) * 8 + lr;
    const uint32_t b2_base = smem_u32(&Bs[b2_kof * KA_AS + 112]);

#pragma unroll
    for (int kc = 0; kc < 7; kc++) {
        uint32_t a0, a1, a2, a3;
        asm volatile("ldmatrix.sync.aligned.m8n8.x4.shared.b16 {%0,%1,%2,%3}, [%4];"
                     : "=r"(a0), "=r"(a1), "=r"(a2), "=r"(a3)
                     : "r"(a_base + kc * 16 * 2));
#pragma unroll
        for (int pr = 0; pr < 7; pr++) {
            uint32_t b0, b1, b2, b3;
            asm volatile("ldmatrix.sync.aligned.m8n8.x4.trans.shared.b16 {%0,%1,%2,%3}, [%4];"
                         : "=r"(b0), "=r"(b1), "=r"(b2), "=r"(b3)
                         : "r"(b_base + (kc * 16 * KA_AS + pr * 16) * 2));
            asm volatile("mma.sync.aligned.m16n8k16.row.col.f32.f16.f16.f32 "
                         "{%0,%1,%2,%3}, {%4,%5,%6,%7}, {%8,%9}, {%0,%1,%2,%3};"
                         : "+f"(acc[2 * pr][0]), "+f"(acc[2 * pr][1]),
                           "+f"(acc[2 * pr][2]), "+f"(acc[2 * pr][3])
                         : "r"(a0), "r"(a1), "r"(a2), "r"(a3), "r"(b0), "r"(b1));
            asm volatile("mma.sync.aligned.m16n8k16.row.col.f32.f16.f16.f32 "
                         "{%0,%1,%2,%3}, {%4,%5,%6,%7}, {%8,%9}, {%0,%1,%2,%3};"
                         : "+f"(acc[2 * pr + 1][0]), "+f"(acc[2 * pr + 1][1]),
                           "+f"(acc[2 * pr + 1][2]), "+f"(acc[2 * pr + 1][3])
                         : "r"(a0), "r"(a1), "r"(a2), "r"(a3), "r"(b2), "r"(b3));
        }
        {
            uint32_t b0, b1;
            asm volatile("ldmatrix.sync.aligned.m8n8.x2.trans.shared.b16 {%0,%1}, [%2];"
                         : "=r"(b0), "=r"(b1)
                         : "r"(b2_base + kc * 16 * KA_AS * 2));
            asm volatile("mma.sync.aligned.m16n8k16.row.col.f32.f16.f16.f32 "
                         "{%0,%1,%2,%3}, {%4,%5,%6,%7}, {%8,%9}, {%0,%1,%2,%3};"
                         : "+f"(acc[14][0]), "+f"(acc[14][1]),
                           "+f"(acc[14][2]), "+f"(acc[14][3])
                         : "r"(a0), "r"(a1), "r"(a2), "r"(a3), "r"(b0), "r"(b1));
        }
    }

    const int row_lo = m0 + warp * 16 + (lane >> 2);
    const int row_hi = row_lo + 8;
#pragma unroll
    for (int nt = 0; nt < 15; nt++) {
        int col = n0 + nt * 8 + (lane & 3) * 2;
        float bias0, bias1;
        if (col < 400)      { bias0 = b[col];        bias1 = b[col + 1]; }
        else if (col < 500) { bias0 = b_t[col - 400]; bias1 = b_t[col - 399]; }
        else                { bias0 = b_s[col - 500]; bias1 = b_s[col - 499]; }
        __half2 lo = __floats2half2_rn(acc[nt][0] + bias0, acc[nt][1] + bias1);
        __half2 hi = __floats2half2_rn(acc[nt][2] + bias0, acc[nt][3] + bias1);
        if (row_lo < LOCN)
            *reinterpret_cast<unsigned*>(&g_Gloc[(size_t)row_lo * 600 + col]) =
                *reinterpret_cast<unsigned*>(&lo);
        if (row_hi < LOCN)
            *reinterpret_cast<unsigned*>(&g_Gloc[(size_t)row_hi * 600 + col]) =
                *reinterpret_cast<unsigned*>(&hi);
    }
}

// =======================================================================
// Kernel B (unchanged)
// =======================================================================
__global__ void kernB(const float* __restrict__ emb_t, const float* __restrict__ W_tt,
                      const float* __restrict__ emb_s, const float* __restrict__ W_ss)
{
    int i = blockIdx.x * blockDim.x + threadIdx.x;
    if (i >= 92 * 100 * 2) return;
    int which = i / 9200;
    int r = i % 9200;
    int s = r / 100, j = r % 100;
    const float* e = which ? emb_s : emb_t;
    const float* W = which ? W_ss : W_tt;
    float acc = 0.f;
#pragma unroll
    for (int d = 0; d < 12; d++) acc += e[s * 12 + d] * W[d * 100 + j];
    (which ? g_Ps : g_Pt)[s * 100 + j] = acc;
}

// =======================================================================
// Kernel C (unchanged)
// =======================================================================
__global__ void kernC(const int* __restrict__ traj,
                      const int* __restrict__ tu, const int* __restrict__ tl,
                      const int* __restrict__ tu_slot, const int* __restrict__ tl_slot,
                      const int* __restrict__ su, const int* __restrict__ sl,
                      const int* __restrict__ su_slot, const int* __restrict__ sl_slot)
{
    const int w = threadIdx.x >> 5, lane = threadIdx.x & 31;
    const int token = blockIdx.x * 8 + w;
    const int bb = token >> 8, t = token & 255;

    const int idx = traj[token];
    const __half* gh = g_Gloc + (size_t)idx * 600;
    __half* sh = g_scr + ((size_t)t * BATCH + bb) * RECW;

    {
        const uint4* gv = (const uint4*)gh;
        uint4* ov = (uint4*)sh;
        for (int q = lane; q < 50; q += 32) ov[q] = gv[q];
    }

    if (lane < 25) {
        const float ut = (float)tu_slot[token], lt = (float)tl_slot[token];
        const float us = (float)su_slot[token], ls = (float)sl_slot[token];
        const float rdt = 1.f / fmaxf(ut + lt, 1.f);
        const float rds = 1.f / fmaxf(us + ls, 1.f);
        const float* Ptl = g_Pt + tl[token] * 100;
        const float* Ptu = g_Pt + tu[token] * 100;
        const float* Psl = g_Ps + sl[token] * 100;
        const float* Psu = g_Ps + su[token] * 100;

        const int j0 = lane * 4;
        float ts[4];
#pragma unroll
        for (int k = 0; k < 4; k++) {
            int j = j0 + k;
            float pt = __half2float(gh[400 + j]) + (ut * Ptl[j] + lt * Ptu[j]) * rdt;
            float ps = __half2float(gh[500 + j]) + (us * Psl[j] + ls * Psu[j]) * rds;
            ts[k] = sigf(pt) * sigf(ps);
        }
        __half2 h01 = __floats2half2_rn(ts[0], ts[1]);
        __half2 h23 = __floats2half2_rn(ts[2], ts[3]);
        uint2 st;
        st.x = *reinterpret_cast<unsigned*>(&h01);
        st.y = *reinterpret_cast<unsigned*>(&h23);
        reinterpret_cast<uint2*>(sh + 400)[lane] = st;
    }
}

// =======================================================================
// Kernel D v10: tensor-core recurrence.
//  Per step, per CTA: preact[7,400] = h[7,100] @ W_hh[100,400] via
//  mma.m16n8k16 (M padded to 16, K to 112). 25 warps, warp w owns cols
//  [16w,16w+16) = 2 n8-tiles. W_hh held as fp16 B-fragments in registers
//  (28 regs/thread, loaded once). h stored fp16 in smem (rows 7-15 and
//  k-pad zeroed once). Per step per warp: 7 ldmatrix.x4 + 14 HMMA, then
//  epilogue (preact add + branch-free activation -> acts smem), barrier,
//  phase-2 LSTM update (c in regs, h -> fp16 STS), barrier.
//  fp16 scratch staged 2 steps ahead via cp.async.bulk.
// =======================================================================
__global__ void __launch_bounds__(800, 1)
kernD(const float* __restrict__ W_hh, float* __restrict__ out)
{
    __shared__ __align__(16) __half hbuf[2][16][HS2];      // 7.7 KB
    __shared__ __align__(16) float  acts[ROWS_PER_CTA][400];
    __shared__ __align__(16) __half sscr[2][ROWS_PER_CTA * RECW];
    __shared__ __align__(8)  ull    smbar[2];

    const int tid = threadIdx.x;
    const int warp = tid >> 5, lane = tid & 31;
    const int row0 = blockIdx.x * ROWS_PER_CTA;

    // ---- B fragments: W_hh fp16, resident. warp w -> cols [16w, 16w+16) ----
    // m16n8k16 B frag: lane holds {B[k0][n],B[k0+1][n]} (reg0), {B[k0+8][n],B[k0+9][n]} (reg1)
    // with k0 = 16c + 2*(lane%4), n = 16w + 8t + lane/4.
    uint32_t bf[7][2][2];
    {
        const int bn = 16 * warp + (lane >> 2);
        const int bk = 2 * (lane & 3);
#pragma unroll
        for (int c = 0; c < 7; c++) {
#pragma unroll
            for (int t = 0; t < 2; t++) {
                int n = bn + 8 * t;
#pragma unroll
                for (int rr = 0; rr < 2; rr++) {
                    int k = 16 * c + bk + 8 * rr;
                    float lo = (k     < 100) ? W_hh[k * 400 + n]       : 0.f;
                    float hi = (k + 1 < 100) ? W_hh[(k + 1) * 400 + n] : 0.f;
                    __half2 hv = __floats2half2_rn(lo, hi);
                    bf[c][t][rr] = *reinterpret_cast<uint32_t*>(&hv);
                }
            }
        }
    }

    // ---- epilogue lane constants ----
    const int erow = lane >> 2;                       // 0..7
    const bool evalid = (erow < ROWS_PER_CTA);        // rows 7..15 ignored
    const int ecol0 = 16 * warp + 2 * (lane & 3);     // tile0 col (even)
    const int ecol1 = ecol0 + 8;                      // tile1 col
    const int g0 = ecol0 / 100, g1 = ecol1 / 100;
    const float as0 = (g0 == 2) ? 2.f : 1.f, aA0 = as0, aB0 = (g0 == 2) ? -1.f : 0.f;
    const float as1 = (g1 == 2) ? 2.f : 1.f, aA1 = as1, aB1 = (g1 == 2) ? -1.f : 0.f;

    // ---- ldmatrix A addresses (per buf): row = lane&15, col = (lane>>4)*8 ----
    const uint32_t la0 = smem_u32(&hbuf[0][lane & 15][(lane >> 4) * 8]);
    const uint32_t la1 = smem_u32(&hbuf[1][lane & 15][(lane >> 4) * 8]);

    // ---- phase-2 assignment ----
    const int r_2 = tid / 100, j_2 = tid % 100;
    const bool p2act = (tid < 700);
    const bool p2out = (row0 + r_2 < BATCH);

    // ---- init smem ----
    {
        uint32_t* hz = (uint32_t*)&hbuf[0][0][0];     // 2*16*120 halfs = 1920 u32
        for (int i = tid; i < 1920; i += 800) hz[i] = 0u;
    }
    uint32_t mb0 = smem_u32(&smbar[0]);
    uint32_t mb1 = smem_u32(&smbar[1]);
    uint32_t sc0 = smem_u32(&sscr[0][0]);
    uint32_t sc1 = smem_u32(&sscr[1][0]);
    if (tid == 0) { mbar_init(mb0, 1); mbar_init(mb1, 1); }
    __syncthreads();

    const __half* scr_base = g_scr + (size_t)row0 * RECW;
    if (tid == 0) {
        mbar_expect_tx(mb0, SCR_BYTES);
        bulk_g2s(sc0, scr_base, SCR_BYTES, mb0);
        mbar_expect_tx(mb1, SCR_BYTES);
        bulk_g2s(sc1, scr_base + (size_t)BATCH * RECW, SCR_BYTES, mb1);
    }

    // loop-invariant pointers
    const __half* pre0a = &sscr[0][0] + erow * RECW + ecol0;
    const __half* pre0b = pre0a + 8;
    const __half* pre1a = &sscr[1][0] + erow * RECW + ecol0;
    const __half* pre1b = pre1a + 8;
    const __half* tsg0 = &sscr[0][0] + r_2 * RECW + 400 + j_2;
    const __half* tsg1 = &sscr[1][0] + r_2 * RECW + 400 + j_2;
    const float*  ap2  = &acts[r_2][j_2];
    __half* hn0 = &hbuf[0][r_2][j_2];                 // phase-2 h store targets
    __half* hn1 = &hbuf[1][r_2][j_2];
    float*  aw0 = &acts[erow < 7 ? erow : 0][ecol0];  // epi store (guarded by evalid)
    float*  outp = out + (row0 + r_2) * 100 + j_2;

    float creg = 0.f;

#define STEPT(BUF, T, PAR, LAB, PA, PB, TSGP, HNP)                              \
    {                                                                           \
        mbar_wait((BUF) ? mb1 : mb0, (PAR));                                    \
        float c0[4] = {0.f, 0.f, 0.f, 0.f};                                     \
        float c1[4] = {0.f, 0.f, 0.f, 0.f};                                     \
        _Pragma("unroll")                                                       \
        for (int c = 0; c < 7; c++) {                                           \
            uint32_t a0, a1, a2, a3;                                            \
            asm volatile("ldmatrix.sync.aligned.m8n8.x4.shared.b16 "            \
                         "{%0,%1,%2,%3}, [%4];"                                 \
                         : "=r"(a0), "=r"(a1), "=r"(a2), "=r"(a3)               \
                         : "r"((LAB) + c * 32));                                \
            asm volatile("mma.sync.aligned.m16n8k16.row.col.f32.f16.f16.f32 "   \
                         "{%0,%1,%2,%3}, {%4,%5,%6,%7}, {%8,%9}, {%0,%1,%2,%3};"\
                         : "+f"(c0[0]), "+f"(c0[1]), "+f"(c0[2]), "+f"(c0[3])   \
                         : "r"(a0), "r"(a1), "r"(a2), "r"(a3),                  \
                           "r"(bf[c][0][0]), "r"(bf[c][0][1]));                 \
            asm volatile("mma.sync.aligned.m16n8k16.row.col.f32.f16.f16.f32 "   \
                         "{%0,%1,%2,%3}, {%4,%5,%6,%7}, {%8,%9}, {%0,%1,%2,%3};"\
                         : "+f"(c1[0]), "+f"(c1[1]), "+f"(c1[2]), "+f"(c1[3])   \
                         : "r"(a0), "r"(a1), "r"(a2), "r"(a3),                  \
                           "r"(bf[c][1][0]), "r"(bf[c][1][1]));                 \
        }                                                                       \
        if (evalid) {                                                           \
            float2 q0 = __half22float2(*(const __half2*)(PA));                  \
            float2 q1 = __half22float2(*(const __half2*)(PB));                  \
            float vA = c0[0] + q0.x, vB = c0[1] + q0.y;                         \
            float vC = c1[0] + q1.x, vD = c1[1] + q1.y;                         \
            float sA = 1.f / (1.f + __expf(-as0 * vA));                         \
            float sB = 1.f / (1.f + __expf(-as0 * vB));                         \
            float sC = 1.f / (1.f + __expf(-as1 * vC));                         \
            float sD = 1.f / (1.f + __expf(-as1 * vD));                         \
            float2 e0 = make_float2(fmaf(sA, aA0, aB0), fmaf(sB, aA0, aB0));    \
            float2 e1 = make_float2(fmaf(sC, aA1, aB1), fmaf(sD, aA1, aB1));    \
            *(float2*)(aw0)     = e0;                                           \
            *(float2*)(aw0 + 8) = e1;                                           \
        }                                                                       \
        __syncthreads();                                                        \
        if (p2act) {                                                            \
            float gi = ap2[0], gf = ap2[100], gg = ap2[200], go = ap2[300];     \
            float tsg = __half2float(*(TSGP));                                  \
            float cN = gf * creg + gi * tsg * gg;                               \
            creg = cN;                                                          \
            float h = go * tanh_fast(cN);                                       \
            *(HNP) = __float2half(h);                                           \
            if ((T) == TSTEPS - 1 && p2out) *outp = h;                          \
        }                                                                       \
        __syncthreads();                                                        \
        if ((T) + 2 < TSTEPS && tid == 0) {                                     \
            uint32_t mb = (BUF) ? mb1 : mb0;                                    \
            mbar_expect_tx(mb, SCR_BYTES);                                      \
            bulk_g2s((BUF) ? sc1 : sc0,                                         \
                     scr_base + (size_t)((T) + 2) * BATCH * RECW, SCR_BYTES, mb); \
        }                                                                       \
    }

#pragma unroll 1
    for (int s = 0; s < TSTEPS / 2; s++) {
        const int par = s & 1;
        const int t0 = 2 * s;
        STEPT(0, t0,     par, la0, pre0a, pre0b, tsg0, hn1)   // read h buf0, write h buf1
        STEPT(1, t0 + 1, par, la1, pre1a, pre1b, tsg1, hn0)   // read h buf1, write h buf0
    }
#undef STEPT
}

// =======================================================================
// launch
// =======================================================================
extern "C" void kernel_launch(void* const* d_in, const int* in_sizes, int n_in,
                              void* d_out, int out_size)
{
    (void)in_sizes; (void)n_in; (void)out_size;
    const int*   traj    = (const int*)d_in[0];
    const int*   tu      = (const int*)d_in[3];
    const int*   tl      = (const int*)d_in[4];
    const int*   tu_s    = (const int*)d_in[5];
    const int*   tl_s    = (const int*)d_in[6];
    const int*   su      = (const int*)d_in[7];
    const int*   sl      = (const int*)d_in[8];
    const int*   su_s    = (const int*)d_in[9];
    const int*   sl_s    = (const int*)d_in[10];
    const float* emb_loc = (const float*)d_in[11];
    const float* emb_t   = (const float*)d_in[12];
    const float* emb_s   = (const float*)d_in[13];
    const float* W_ih    = (const float*)d_in[14];
    const float* W_hh    = (const float*)d_in[15];
    const float* b       = (const float*)d_in[16];
    const float* W_xt    = (const float*)d_in[17];
    const float* W_tt    = (const float*)d_in[18];
    const float* b_t     = (const float*)d_in[19];
    const float* W_xs    = (const float*)d_in[20];
    const float* W_ss    = (const float*)d_in[21];
    const float* b_s     = (const float*)d_in[22];
    float* out = (float*)d_out;

    dim3 gA(5, (LOCN + 63) / 64);
    kernA<<<gA, 128>>>(emb_loc, W_ih, W_xt, W_xs, b, b_t, b_s);

    kernB<<<(92 * 100 * 2 + 255) / 256, 256>>>(emb_t, W_tt, emb_s, W_ss);

    kernC<<<(BATCH * TSTEPS) / 8, 256>>>(traj, tu, tl, tu_s, tl_s, su, sl, su_s, sl_s);

    kernD<<<NCTA, 800>>>(W_hh, out);
}

// round 12
// speedup vs baseline: 3.1982x; 1.1618x over previous
#include <cuda_runtime.h>
#include <cuda_fp16.h>
#include <cstdint>

typedef unsigned long long ull;

#define LOCN   40001
#define BATCH  1024
#define TSTEPS 256

#define ROWS_PER_CTA 7
#define NCTA ((BATCH + ROWS_PER_CTA - 1) / ROWS_PER_CTA)   // 147
#define HS2 120                              // fp16 h row stride (conflict-free ldmatrix)
#define SRW 608                              // staging row stride in halfs (16B-mult)

// dynamic smem layout (bytes)
#define OFF_HBUF 0                            // 2*16*120*2      = 7680
#define OFF_ACTS 7680                         // 7*400*4         = 11200
#define OFF_STG  18880                        // 3*7*608*2       = 25536
#define OFF_TRAJ 44416                        // 7*256*2         = 3584
#define OFF_IDX  48000                        // 7*256*8         = 14336
#define OFF_PT   62336                        // 9200*2          = 18400
#define OFF_PS   80736                        // 9200*2          = 18400
#define DSM_TOTAL 99136

// ---------------- device scratch ----------------
__device__ __half g_Gloc[(size_t)LOCN * 600];                  // fp16: 48 MB (L2-resident)
__device__ float  g_Pt[92 * 100];
__device__ float  g_Ps[92 * 100];

// ---------------- helpers ----------------
__device__ __forceinline__ float sigf(float x) { return 1.f / (1.f + __expf(-x)); }
__device__ __forceinline__ float tanh_fast(float x) { return 1.f - 2.f / (1.f + __expf(2.f * x)); }

__device__ __forceinline__ ull pack2(float lo, float hi) {
    ull r; asm("mov.b64 %0, {%1, %2};" : "=l"(r) : "f"(lo), "f"(hi)); return r;
}
__device__ __forceinline__ void unpack2(ull v, float& lo, float& hi) {
    asm("mov.b64 {%0, %1}, %2;" : "=f"(lo), "=f"(hi) : "l"(v));
}
__device__ __forceinline__ void fma2(ull& acc, ull a, ull b) {
    asm("fma.rn.f32x2 %0, %1, %2, %0;" : "+l"(acc) : "l"(a), "l"(b));
}
__device__ __forceinline__ uint32_t smem_u32(const void* p) {
    uint32_t a;
    asm("{ .reg .u64 t; cvta.to.shared.u64 t, %1; cvt.u32.u64 %0, t; }" : "=r"(a) : "l"(p));
    return a;
}

// =======================================================================
// Kernel A (tensor-core): Gloc = fp16( emb_loc @ [W_ih|W_xt|W_xs] + bias )
// (unchanged from R10/R11)
// =======================================================================
#define KA_AS 120

__global__ void __launch_bounds__(128)
kernA(const float* __restrict__ emb_loc,
      const float* __restrict__ W_ih,
      const float* __restrict__ W_xt,
      const float* __restrict__ W_xs,
      const float* __restrict__ b,
      const float* __restrict__ b_t,
      const float* __restrict__ b_s)
{
    __shared__ __align__(16) __half As[64 * KA_AS];
    __shared__ __align__(16) __half Bs[112 * KA_AS];

    const int tid = threadIdx.x;
    const int warp = tid >> 5, lane = tid & 31;
    const int n0 = blockIdx.x * 120;
    const int m0 = blockIdx.y * 64;

    for (int i = tid; i < 64 * 112; i += 128) {
        int r = i / 112, k = i % 112;
        int row = m0 + r;
        float v = (row < LOCN && k < 100) ? emb_loc[(size_t)row * 100 + k] : 0.f;
        As[r * KA_AS + k] = __float2half(v);
    }
    for (int i = tid; i < 112 * 120; i += 128) {
        int k = i / 120, c = i % 120;
        int col = n0 + c;
        float v = 0.f;
        if (k < 100) {
            if (col < 400)      v = W_ih[k * 400 + col];
            else if (col < 500) v = W_xt[k * 100 + (col - 400)];
            else                v = W_xs[k * 100 + (col - 500)];
        }
        Bs[k * KA_AS + c] = __float2half(v);
    }
    __syncthreads();

    const int g8 = lane >> 3, lr = lane & 7;

    float acc[15][4];
#pragma unroll
    for (int i = 0; i < 15; i++) { acc[i][0] = acc[i][1] = acc[i][2] = acc[i][3] = 0.f; }

    const int a_row = warp * 16 + (g8 & 1) * 8 + lr;
    const int a_kof = (g8 >> 1) * 8;
    const uint32_t a_base = smem_u32(&As[a_row * KA_AS + a_kof]);
    const int b_kof = (g8 & 1) * 8 + lr;
    const int b_nof = (g8 >> 1) * 8;
    const uint32_t b_base = smem_u32(&Bs[b_kof * KA_AS + b_nof]);
    const int b2_kof = ((lane >> 3) & 1) * 8 + lr;
    const uint32_t b2_base = smem_u32(&Bs[b2_kof * KA_AS + 112]);

#pragma unroll
    for (int kc = 0; kc < 7; kc++) {
        uint32_t a0, a1, a2, a3;
        asm volatile("ldmatrix.sync.aligned.m8n8.x4.shared.b16 {%0,%1,%2,%3}, [%4];"
                     : "=r"(a0), "=r"(a1), "=r"(a2), "=r"(a3)
                     : "r"(a_base + kc * 16 * 2));
#pragma unroll
        for (int pr = 0; pr < 7; pr++) {
            uint32_t b0, b1, b2, b3;
            asm volatile("ldmatrix.sync.aligned.m8n8.x4.trans.shared.b16 {%0,%1,%2,%3}, [%4];"
                         : "=r"(b0), "=r"(b1), "=r"(b2), "=r"(b3)
                         : "r"(b_base + (kc * 16 * KA_AS + pr * 16) * 2));
            asm volatile("mma.sync.aligned.m16n8k16.row.col.f32.f16.f16.f32 "
                         "{%0,%1,%2,%3}, {%4,%5,%6,%7}, {%8,%9}, {%0,%1,%2,%3};"
                         : "+f"(acc[2 * pr][0]), "+f"(acc[2 * pr][1]),
                           "+f"(acc[2 * pr][2]), "+f"(acc[2 * pr][3])
                         : "r"(a0), "r"(a1), "r"(a2), "r"(a3), "r"(b0), "r"(b1));
            asm volatile("mma.sync.aligned.m16n8k16.row.col.f32.f16.f16.f32 "
                         "{%0,%1,%2,%3}, {%4,%5,%6,%7}, {%8,%9}, {%0,%1,%2,%3};"
                         : "+f"(acc[2 * pr + 1][0]), "+f"(acc[2 * pr + 1][1]),
                           "+f"(acc[2 * pr + 1][2]), "+f"(acc[2 * pr + 1][3])
                         : "r"(a0), "r"(a1), "r"(a2), "r"(a3), "r"(b2), "r"(b3));
        }
        {
            uint32_t b0, b1;
            asm volatile("ldmatrix.sync.aligned.m8n8.x2.trans.shared.b16 {%0,%1}, [%2];"
                         : "=r"(b0), "=r"(b1)
                         : "r"(b2_base + kc * 16 * KA_AS * 2));
            asm volatile("mma.sync.aligned.m16n8k16.row.col.f32.f16.f16.f32 "
                         "{%0,%1,%2,%3}, {%4,%5,%6,%7}, {%8,%9}, {%0,%1,%2,%3};"
                         : "+f"(acc[14][0]), "+f"(acc[14][1]),
                           "+f"(acc[14][2]), "+f"(acc[14][3])
                         : "r"(a0), "r"(a1), "r"(a2), "r"(a3), "r"(b0), "r"(b1));
        }
    }

    const int row_lo = m0 + warp * 16 + (lane >> 2);
    const int row_hi = row_lo + 8;
#pragma unroll
    for (int nt = 0; nt < 15; nt++) {
        int col = n0 + nt * 8 + (lane & 3) * 2;
        float bias0, bias1;
        if (col < 400)      { bias0 = b[col];        bias1 = b[col + 1]; }
        else if (col < 500) { bias0 = b_t[col - 400]; bias1 = b_t[col - 399]; }
        else                { bias0 = b_s[col - 500]; bias1 = b_s[col - 499]; }
        __half2 lo = __floats2half2_rn(acc[nt][0] + bias0, acc[nt][1] + bias1);
        __half2 hi = __floats2half2_rn(acc[nt][2] + bias0, acc[nt][3] + bias1);
        if (row_lo < LOCN)
            *reinterpret_cast<unsigned*>(&g_Gloc[(size_t)row_lo * 600 + col]) =
                *reinterpret_cast<unsigned*>(&lo);
        if (row_hi < LOCN)
            *reinterpret_cast<unsigned*>(&g_Gloc[(size_t)row_hi * 600 + col]) =
                *reinterpret_cast<unsigned*>(&hi);
    }
}

// =======================================================================
// Kernel B (unchanged)
// =======================================================================
__global__ void kernB(const float* __restrict__ emb_t, const float* __restrict__ W_tt,
                      const float* __restrict__ emb_s, const float* __restrict__ W_ss)
{
    int i = blockIdx.x * blockDim.x + threadIdx.x;
    if (i >= 92 * 100 * 2) return;
    int which = i / 9200;
    int r = i % 9200;
    int s = r / 100, j = r % 100;
    const float* e = which ? emb_s : emb_t;
    const float* W = which ? W_ss : W_tt;
    float acc = 0.f;
#pragma unroll
    for (int d = 0; d < 12; d++) acc += e[s * 12 + d] * W[d * 100 + j];
    (which ? g_Ps : g_Pt)[s * 100 + j] = acc;
}

// =======================================================================
// Kernel D v11: fused gather + tensor-core recurrence (kernC eliminated).
//  Per step: preact[7,400] = h[7,100] @ W_hh via mma.m16n8k16 (W_hh fp16
//  B-fragments resident in regs). Gloc rows gathered per step directly
//  into triple-buffered smem staging via cp.async.cg (2 steps ahead).
//  tsg computed inline in phase 2 from fp16 Pt/Ps tables (smem) + packed
//  slot indices (smem). 2 barriers per step.
// =======================================================================
__global__ void __launch_bounds__(800, 1)
kernD(const float* __restrict__ W_hh, float* __restrict__ out,
      const int* __restrict__ traj,
      const int* __restrict__ tu,   const int* __restrict__ tl,
      const int* __restrict__ tu_s, const int* __restrict__ tl_s,
      const int* __restrict__ su,   const int* __restrict__ sl,
      const int* __restrict__ su_s, const int* __restrict__ sl_s)
{
    extern __shared__ __align__(16) char dsm[];
    __half*   hbuf  = (__half*)(dsm + OFF_HBUF);   // [2][16][120]
    float*    acts  = (float*)(dsm + OFF_ACTS);    // [7][400]
    __half*   stg   = (__half*)(dsm + OFF_STG);    // [3][7][608]
    uint16_t* trajS = (uint16_t*)(dsm + OFF_TRAJ); // [7][256]
    uint2*    idx8  = (uint2*)(dsm + OFF_IDX);     // [7][256]
    __half*   PtS   = (__half*)(dsm + OFF_PT);     // [92][100]
    __half*   PsS   = (__half*)(dsm + OFF_PS);

    const int tid = threadIdx.x;
    const int warp = tid >> 5, lane = tid & 31;
    const int row0 = blockIdx.x * ROWS_PER_CTA;

    // ---- B fragments: W_hh fp16, resident ----
    uint32_t bf[7][2][2];
    {
        const int bn = 16 * warp + (lane >> 2);
        const int bk = 2 * (lane & 3);
#pragma unroll
        for (int c = 0; c < 7; c++) {
#pragma unroll
            for (int t = 0; t < 2; t++) {
                int n = bn + 8 * t;
#pragma unroll
                for (int rr = 0; rr < 2; rr++) {
                    int k = 16 * c + bk + 8 * rr;
                    float lo = (k     < 100) ? W_hh[k * 400 + n]       : 0.f;
                    float hi = (k + 1 < 100) ? W_hh[(k + 1) * 400 + n] : 0.f;
                    __half2 hv = __floats2half2_rn(lo, hi);
                    bf[c][t][rr] = *reinterpret_cast<uint32_t*>(&hv);
                }
            }
        }
    }

    // ---- epilogue lane constants ----
    const int erow = lane >> 2;
    const bool evalid = (erow < ROWS_PER_CTA);
    const int ecol0 = 16 * warp + 2 * (lane & 3);
    const int g0 = ecol0 / 100, g1 = (ecol0 + 8) / 100;
    const float as0 = (g0 == 2) ? 2.f : 1.f, aA0 = as0, aB0 = (g0 == 2) ? -1.f : 0.f;
    const float as1 = (g1 == 2) ? 2.f : 1.f, aA1 = as1, aB1 = (g1 == 2) ? -1.f : 0.f;
    const int eoffA = (erow < 7 ? erow : 0) * SRW + ecol0;   // staging preact offset (halfs)

    // ---- ldmatrix A addresses per hbuf ----
    const uint32_t la0 = smem_u32(hbuf + (lane & 15) * HS2 + (lane >> 4) * 8);
    const uint32_t la1 = la0 + 16 * HS2 * 2;

    // ---- phase-2 assignment ----
    const int r_2 = tid / 100, j_2 = tid % 100;
    const bool p2act = (tid < 700);
    const bool p2out = (row0 + r_2 < BATCH);
    const int p2off = r_2 * SRW + 400 + j_2;                 // tpre offset in staging

    // ---- staging thread roles ----
    const bool sact = (tid < 525);
    const int r_s = tid / 75, c_s = tid % 75;
    const uint32_t stg_u32 = smem_u32(stg);

    // ---- init smem ----
    {
        uint32_t* hz = (uint32_t*)hbuf;                      // 1920 u32
        for (int i = tid; i < 1920; i += 800) hz[i] = 0u;
        for (int i = tid; i < 9200; i += 800) {
            PtS[i] = __float2half(g_Pt[i]);
            PsS[i] = __float2half(g_Ps[i]);
        }
        for (int i = tid; i < 7 * 256; i += 800) {
            int r = i >> 8, tt = i & 255;
            int rr = min(row0 + r, BATCH - 1);
            int g = rr * 256 + tt;
            trajS[i] = (uint16_t)traj[g];
            uint32_t A = (uint32_t)tu[g] | ((uint32_t)tl[g] << 8) |
                         ((uint32_t)su[g] << 16) | ((uint32_t)sl[g] << 24);
            uint32_t B = (uint32_t)tu_s[g] | ((uint32_t)tl_s[g] << 8) |
                         ((uint32_t)su_s[g] << 16) | ((uint32_t)sl_s[g] << 24);
            idx8[i] = make_uint2(A, B);
        }
    }
    __syncthreads();

#define ISSUE(TT, B3)                                                           \
    {                                                                           \
        if (sact && (TT) < TSTEPS) {                                            \
            int gidx = (int)trajS[(r_s << 8) + (TT)];                           \
            const __half* srcp = g_Gloc + (size_t)gidx * 600 + c_s * 8;         \
            uint32_t dstp = stg_u32 + (uint32_t)(((B3) * 7 + r_s) * SRW + c_s * 8) * 2; \
            asm volatile("cp.async.cg.shared.global [%0], [%1], 16;"            \
                         :: "r"(dstp), "l"(srcp) : "memory");                   \
        }                                                                       \
        asm volatile("cp.async.commit_group;" ::: "memory");                    \
    }

    // prologue: stage t=0 (buf0), t=1 (buf1)
    ISSUE(0, 0)
    ISSUE(1, 1)
    asm volatile("cp.async.wait_group 1;" ::: "memory");
    __syncthreads();

    float creg = 0.f;
    float* outp = out + (row0 + r_2) * 100 + j_2;
    float* aw0 = acts + (erow < 7 ? erow : 0) * 400 + ecol0;
    const float* ap2 = acts + r_2 * 400 + j_2;
    __half* hn0 = hbuf + r_2 * HS2 + j_2;
    __half* hn1 = hn0 + 16 * HS2;

#define STEPT(T, LAB, B3R, B3W, HNP)                                            \
    {                                                                           \
        const __half* stgR = stg + (B3R) * (7 * SRW);                           \
        float c0[4] = {0.f, 0.f, 0.f, 0.f};                                     \
        float c1[4] = {0.f, 0.f, 0.f, 0.f};                                     \
        _Pragma("unroll")                                                       \
        for (int c = 0; c < 7; c++) {                                           \
            uint32_t a0, a1, a2, a3;                                            \
            asm volatile("ldmatrix.sync.aligned.m8n8.x4.shared.b16 "            \
                         "{%0,%1,%2,%3}, [%4];"                                 \
                         : "=r"(a0), "=r"(a1), "=r"(a2), "=r"(a3)               \
                         : "r"((LAB) + c * 32));                                \
            asm volatile("mma.sync.aligned.m16n8k16.row.col.f32.f16.f16.f32 "   \
                         "{%0,%1,%2,%3}, {%4,%5,%6,%7}, {%8,%9}, {%0,%1,%2,%3};"\
                         : "+f"(c0[0]), "+f"(c0[1]), "+f"(c0[2]), "+f"(c0[3])   \
                         : "r"(a0), "r"(a1), "r"(a2), "r"(a3),                  \
                           "r"(bf[c][0][0]), "r"(bf[c][0][1]));                 \
            asm volatile("mma.sync.aligned.m16n8k16.row.col.f32.f16.f16.f32 "   \
                         "{%0,%1,%2,%3}, {%4,%5,%6,%7}, {%8,%9}, {%0,%1,%2,%3};"\
                         : "+f"(c1[0]), "+f"(c1[1]), "+f"(c1[2]), "+f"(c1[3])   \
                         : "r"(a0), "r"(a1), "r"(a2), "r"(a3),                  \
                           "r"(bf[c][1][0]), "r"(bf[c][1][1]));                 \
        }                                                                       \
        if (evalid) {                                                           \
            float2 q0 = __half22float2(*(const __half2*)(stgR + eoffA));        \
            float2 q1 = __half22float2(*(const __half2*)(stgR + eoffA + 8));    \
            float vA = c0[0] + q0.x, vB = c0[1] + q0.y;                         \
            float vC = c1[0] + q1.x, vD = c1[1] + q1.y;                         \
            float sA = 1.f / (1.f + __expf(-as0 * vA));                         \
            float sB = 1.f / (1.f + __expf(-as0 * vB));                         \
            float sC = 1.f / (1.f + __expf(-as1 * vC));                         \
            float sD = 1.f / (1.f + __expf(-as1 * vD));                         \
            float2 e0 = make_float2(fmaf(sA, aA0, aB0), fmaf(sB, aA0, aB0));    \
            float2 e1 = make_float2(fmaf(sC, aA1, aB1), fmaf(sD, aA1, aB1));    \
            *(float2*)(aw0)     = e0;                                           \
            *(float2*)(aw0 + 8) = e1;                                           \
        }                                                                       \
        __syncthreads();                                                        \
        if (p2act) {                                                            \
            float gi = ap2[0], gf = ap2[100], gg = ap2[200], go = ap2[300];     \
            uint2 pk = idx8[(r_2 << 8) + (T)];                                  \
            int tui = pk.x & 0xff, tli = (pk.x >> 8) & 0xff;                    \
            int sui = (pk.x >> 16) & 0xff, sli = pk.x >> 24;                    \
            float utv = (float)(pk.y & 0xff), ltv = (float)((pk.y >> 8) & 0xff);\
            float usv = (float)((pk.y >> 16) & 0xff), lsv = (float)(pk.y >> 24);\
            float rdt = __fdividef(1.f, fmaxf(utv + ltv, 1.f));                 \
            float rds = __fdividef(1.f, fmaxf(usv + lsv, 1.f));                 \
            float tpre = __half2float(stgR[p2off]);                             \
            float spre = __half2float(stgR[p2off + 100]);                       \
            float pt = tpre + (utv * __half2float(PtS[tli * 100 + j_2])         \
                             + ltv * __half2float(PtS[tui * 100 + j_2])) * rdt; \
            float ps = spre + (usv * __half2float(PsS[sli * 100 + j_2])         \
                             + lsv * __half2float(PsS[sui * 100 + j_2])) * rds; \
            float tsg = sigf(pt) * sigf(ps);                                    \
            float cN = gf * creg + gi * tsg * gg;                               \
            creg = cN;                                                          \
            float h = go * tanh_fast(cN);                                       \
            *(HNP) = __float2half(h);                                           \
            if ((T) == TSTEPS - 1 && p2out) *outp = h;                          \
        }                                                                       \
        ISSUE((T) + 2, B3W)                                                     \
        asm volatile("cp.async.wait_group 1;" ::: "memory");                    \
        __syncthreads();                                                        \
    }

    int b3a = 0;
#pragma unroll 1
    for (int s = 0; s < TSTEPS / 2; s++) {
        const int t0 = 2 * s;
        const int b3b  = (b3a == 2) ? 0 : b3a + 1;
        const int b3w0 = (b3b == 2) ? 0 : b3b + 1;
        const int b3w1 = b3a;
        STEPT(t0,     la0, b3a, b3w0, hn1)   // h in buf0, write h to buf1
        STEPT(t0 + 1, la1, b3b, b3w1, hn0)   // h in buf1, write h to buf0
        b3a = b3w0;
    }
#undef STEPT
#undef ISSUE
}

// =======================================================================
// launch
// =======================================================================
extern "C" void kernel_launch(void* const* d_in, const int* in_sizes, int n_in,
                              void* d_out, int out_size)
{
    (void)in_sizes; (void)n_in; (void)out_size;
    const int*   traj    = (const int*)d_in[0];
    const int*   tu      = (const int*)d_in[3];
    const int*   tl      = (const int*)d_in[4];
    const int*   tu_s    = (const int*)d_in[5];
    const int*   tl_s    = (const int*)d_in[6];
    const int*   su      = (const int*)d_in[7];
    const int*   sl      = (const int*)d_in[8];
    const int*   su_s    = (const int*)d_in[9];
    const int*   sl_s    = (const int*)d_in[10];
    const float* emb_loc = (const float*)d_in[11];
    const float* emb_t   = (const float*)d_in[12];
    const float* emb_s   = (const float*)d_in[13];
    const float* W_ih    = (const float*)d_in[14];
    const float* W_hh    = (const float*)d_in[15];
    const float* b       = (const float*)d_in[16];
    const float* W_xt    = (const float*)d_in[17];
    const float* W_tt    = (const float*)d_in[18];
    const float* b_t     = (const float*)d_in[19];
    const float* W_xs    = (const float*)d_in[20];
    const float* W_ss    = (const float*)d_in[21];
    const float* b_s     = (const float*)d_in[22];
    float* out = (float*)d_out;

    static bool attr_set = false;
    if (!attr_set) {
        cudaFuncSetAttribute(kernD, cudaFuncAttributeMaxDynamicSharedMemorySize,
                             DSM_TOTAL);
        attr_set = true;
    }

    dim3 gA(5, (LOCN + 63) / 64);
    kernA<<<gA, 128>>>(emb_loc, W_ih, W_xt, W_xs, b, b_t, b_s);

    kernB<<<(92 * 100 * 2 + 255) / 256, 256>>>(emb_t, W_tt, emb_s, W_ss);

    kernD<<<NCTA, 800, DSM_TOTAL>>>(W_hh, out, traj,
                                    tu, tl, tu_s, tl_s, su, sl, su_s, sl_s);
}

// round 13
// speedup vs baseline: 3.8192x; 1.1942x over previous
#include <cuda_runtime.h>
#include <cuda_fp16.h>
#include <cstdint>

typedef unsigned long long ull;

#define LOCN   40001
#define BATCH  1024
#define TSTEPS 256

#define ROWS_PER_CTA 7
#define NCTA ((BATCH + ROWS_PER_CTA - 1) / ROWS_PER_CTA)   // 147
#define HS2 120                              // fp16 h row stride (conflict-free ldmatrix)
#define SRW 608                              // staging row stride in halfs (16B-mult)

// dynamic smem layout for kernD (bytes)
#define OFF_HBUF 0                            // 2*16*120*2      = 7680
#define OFF_ACTS 7680                         // 7*400*4         = 11200
#define OFF_STG  18880                        // 3*7*608*2       = 25536
#define OFF_TRAJ 44416                        // 7*256*2         = 3584
#define OFF_IDX  48000                        // 7*256*8         = 14336
#define OFF_PT   62336                        // 9200*2          = 18400
#define OFF_PS   80736                        // 9200*2          = 18400
#define DSM_TOTAL 99136

// ---------------- device scratch ----------------
__device__ __half g_Gloc[(size_t)LOCN * 600];                  // fp16: 48 MB (L2-resident)
__device__ float  g_Pt[92 * 100];
__device__ float  g_Ps[92 * 100];
__device__ __half g_emb16[(size_t)LOCN * 112];                 // fp16 emb_loc, k-padded
__device__ __half g_W16[112 * 608];                            // fp16 [W_ih|W_xt|W_xs], padded

// ---------------- helpers ----------------
__device__ __forceinline__ float sigf(float x) { return 1.f / (1.f + __expf(-x)); }
__device__ __forceinline__ float tanh_fast(float x) { return 1.f - 2.f / (1.f + __expf(2.f * x)); }

__device__ __forceinline__ uint32_t smem_u32(const void* p) {
    uint32_t a;
    asm("{ .reg .u64 t; cvta.to.shared.u64 t, %1; cvt.u32.u64 %0, t; }" : "=r"(a) : "l"(p));
    return a;
}

// =======================================================================
// Kernel P: one-time fp16 conversion of emb_loc and the fused weight matrix
// =======================================================================
__global__ void kernP(const float* __restrict__ emb_loc,
                      const float* __restrict__ W_ih,
                      const float* __restrict__ W_xt,
                      const float* __restrict__ W_xs)
{
    const int NE = LOCN * 28;                 // emb: groups of 4 halfs
    int i = blockIdx.x * blockDim.x + threadIdx.x;
    if (i < NE) {
        int row = i / 28, k4 = i % 28;
        int k = k4 * 4;
        float4 v = make_float4(0.f, 0.f, 0.f, 0.f);
        if (k < 100) v = *(const float4*)(emb_loc + (size_t)row * 100 + k);
        __half2 h0 = __floats2half2_rn(v.x, v.y);
        __half2 h1 = __floats2half2_rn(v.z, v.w);
        uint2 st;
        st.x = *reinterpret_cast<unsigned*>(&h0);
        st.y = *reinterpret_cast<unsigned*>(&h1);
        *(uint2*)(g_emb16 + (size_t)row * 112 + k) = st;
    } else {
        int j = i - NE;
        if (j < 112 * 152) {
            int k = j / 152, c4 = j % 152;
            int c = c4 * 4;
            float v[4] = {0.f, 0.f, 0.f, 0.f};
            if (k < 100) {
#pragma unroll
                for (int d = 0; d < 4; d++) {
                    int col = c + d;
                    if (col < 400)      v[d] = W_ih[k * 400 + col];
                    else if (col < 500) v[d] = W_xt[k * 100 + (col - 400)];
                    else if (col < 600) v[d] = W_xs[k * 100 + (col - 500)];
                }
            }
            __half2 h0 = __floats2half2_rn(v[0], v[1]);
            __half2 h1 = __floats2half2_rn(v[2], v[3]);
            uint2 st;
            st.x = *reinterpret_cast<unsigned*>(&h0);
            st.y = *reinterpret_cast<unsigned*>(&h1);
            *(uint2*)(g_W16 + k * 608 + c) = st;
        }
    }
}

// =======================================================================
// Kernel A v2 (tensor-core, fp16 inputs): Gloc = fp16(emb16 @ W16 + bias)
//  Tile loads are pure uint4 copies from pre-converted fp16 globals.
// =======================================================================
#define KA_AS 120

__global__ void __launch_bounds__(128)
kernA(const float* __restrict__ b,
      const float* __restrict__ b_t,
      const float* __restrict__ b_s)
{
    __shared__ __align__(16) __half As[64 * KA_AS];
    __shared__ __align__(16) __half Bs[112 * KA_AS];

    const int tid = threadIdx.x;
    const int warp = tid >> 5, lane = tid & 31;
    const int n0 = blockIdx.x * 120;
    const int m0 = blockIdx.y * 64;

    // ---- A tile: 64 rows x 14 uint4 (rows clamped; dup rows are discarded) ----
    for (int i = tid; i < 64 * 14; i += 128) {
        int r = i / 14, c = i % 14;
        int row = m0 + r; if (row >= LOCN) row = LOCN - 1;
        uint4 v = *(const uint4*)(g_emb16 + (size_t)row * 112 + c * 8);
        *(uint4*)(As + r * KA_AS + c * 8) = v;
    }
    // ---- B tile: 112 rows x 15 uint4 ----
    for (int i = tid; i < 112 * 15; i += 128) {
        int k = i / 15, c = i % 15;
        uint4 v = *(const uint4*)(g_W16 + k * 608 + n0 + c * 8);
        *(uint4*)(Bs + k * KA_AS + c * 8) = v;
    }
    __syncthreads();

    const int g8 = lane >> 3, lr = lane & 7;

    float acc[15][4];
#pragma unroll
    for (int i = 0; i < 15; i++) { acc[i][0] = acc[i][1] = acc[i][2] = acc[i][3] = 0.f; }

    const int a_row = warp * 16 + (g8 & 1) * 8 + lr;
    const int a_kof = (g8 >> 1) * 8;
    const uint32_t a_base = smem_u32(&As[a_row * KA_AS + a_kof]);
    const int b_kof = (g8 & 1) * 8 + lr;
    const int b_nof = (g8 >> 1) * 8;
    const uint32_t b_base = smem_u32(&Bs[b_kof * KA_AS + b_nof]);
    const int b2_kof = ((lane >> 3) & 1) * 8 + lr;
    const uint32_t b2_base = smem_u32(&Bs[b2_kof * KA_AS + 112]);

#pragma unroll
    for (int kc = 0; kc < 7; kc++) {
        uint32_t a0, a1, a2, a3;
        asm volatile("ldmatrix.sync.aligned.m8n8.x4.shared.b16 {%0,%1,%2,%3}, [%4];"
                     : "=r"(a0), "=r"(a1), "=r"(a2), "=r"(a3)
                     : "r"(a_base + kc * 16 * 2));
#pragma unroll
        for (int pr = 0; pr < 7; pr++) {
            uint32_t b0, b1, b2, b3;
            asm volatile("ldmatrix.sync.aligned.m8n8.x4.trans.shared.b16 {%0,%1,%2,%3}, [%4];"
                         : "=r"(b0), "=r"(b1), "=r"(b2), "=r"(b3)
                         : "r"(b_base + (kc * 16 * KA_AS + pr * 16) * 2));
            asm volatile("mma.sync.aligned.m16n8k16.row.col.f32.f16.f16.f32 "
                         "{%0,%1,%2,%3}, {%4,%5,%6,%7}, {%8,%9}, {%0,%1,%2,%3};"
                         : "+f"(acc[2 * pr][0]), "+f"(acc[2 * pr][1]),
                           "+f"(acc[2 * pr][2]), "+f"(acc[2 * pr][3])
                         : "r"(a0), "r"(a1), "r"(a2), "r"(a3), "r"(b0), "r"(b1));
            asm volatile("mma.sync.aligned.m16n8k16.row.col.f32.f16.f16.f32 "
                         "{%0,%1,%2,%3}, {%4,%5,%6,%7}, {%8,%9}, {%0,%1,%2,%3};"
                         : "+f"(acc[2 * pr + 1][0]), "+f"(acc[2 * pr + 1][1]),
                           "+f"(acc[2 * pr + 1][2]), "+f"(acc[2 * pr + 1][3])
                         : "r"(a0), "r"(a1), "r"(a2), "r"(a3), "r"(b2), "r"(b3));
        }
        {
            uint32_t b0, b1;
            asm volatile("ldmatrix.sync.aligned.m8n8.x2.trans.shared.b16 {%0,%1}, [%2];"
                         : "=r"(b0), "=r"(b1)
                         : "r"(b2_base + kc * 16 * KA_AS * 2));
            asm volatile("mma.sync.aligned.m16n8k16.row.col.f32.f16.f16.f32 "
                         "{%0,%1,%2,%3}, {%4,%5,%6,%7}, {%8,%9}, {%0,%1,%2,%3};"
                         : "+f"(acc[14][0]), "+f"(acc[14][1]),
                           "+f"(acc[14][2]), "+f"(acc[14][3])
                         : "r"(a0), "r"(a1), "r"(a2), "r"(a3), "r"(b0), "r"(b1));
        }
    }

    const int row_lo = m0 + warp * 16 + (lane >> 2);
    const int row_hi = row_lo + 8;
#pragma unroll
    for (int nt = 0; nt < 15; nt++) {
        int col = n0 + nt * 8 + (lane & 3) * 2;
        float bias0, bias1;
        if (col < 400)      { bias0 = b[col];        bias1 = b[col + 1]; }
        else if (col < 500) { bias0 = b_t[col - 400]; bias1 = b_t[col - 399]; }
        else                { bias0 = b_s[col - 500]; bias1 = b_s[col - 499]; }
        __half2 lo = __floats2half2_rn(acc[nt][0] + bias0, acc[nt][1] + bias1);
        __half2 hi = __floats2half2_rn(acc[nt][2] + bias0, acc[nt][3] + bias1);
        if (row_lo < LOCN)
            *reinterpret_cast<unsigned*>(&g_Gloc[(size_t)row_lo * 600 + col]) =
                *reinterpret_cast<unsigned*>(&lo);
        if (row_hi < LOCN)
            *reinterpret_cast<unsigned*>(&g_Gloc[(size_t)row_hi * 600 + col]) =
                *reinterpret_cast<unsigned*>(&hi);
    }
}

// =======================================================================
// Kernel B (unchanged)
// =======================================================================
__global__ void kernB(const float* __restrict__ emb_t, const float* __restrict__ W_tt,
                      const float* __restrict__ emb_s, const float* __restrict__ W_ss)
{
    int i = blockIdx.x * blockDim.x + threadIdx.x;
    if (i >= 92 * 100 * 2) return;
    int which = i / 9200;
    int r = i % 9200;
    int s = r / 100, j = r % 100;
    const float* e = which ? emb_s : emb_t;
    const float* W = which ? W_ss : W_tt;
    float acc = 0.f;
#pragma unroll
    for (int d = 0; d < 12; d++) acc += e[s * 12 + d] * W[d * 100 + j];
    (which ? g_Ps : g_Pt)[s * 100 + j] = acc;
}

// =======================================================================
// Kernel D (unchanged from R12): fused gather + tensor-core recurrence.
// =======================================================================
__global__ void __launch_bounds__(800, 1)
kernD(const float* __restrict__ W_hh, float* __restrict__ out,
      const int* __restrict__ traj,
      const int* __restrict__ tu,   const int* __restrict__ tl,
      const int* __restrict__ tu_s, const int* __restrict__ tl_s,
      const int* __restrict__ su,   const int* __restrict__ sl,
      const int* __restrict__ su_s, const int* __restrict__ sl_s)
{
    extern __shared__ __align__(16) char dsm[];
    __half*   hbuf  = (__half*)(dsm + OFF_HBUF);   // [2][16][120]
    float*    acts  = (float*)(dsm + OFF_ACTS);    // [7][400]
    __half*   stg   = (__half*)(dsm + OFF_STG);    // [3][7][608]
    uint16_t* trajS = (uint16_t*)(dsm + OFF_TRAJ); // [7][256]
    uint2*    idx8  = (uint2*)(dsm + OFF_IDX);     // [7][256]
    __half*   PtS   = (__half*)(dsm + OFF_PT);     // [92][100]
    __half*   PsS   = (__half*)(dsm + OFF_PS);

    const int tid = threadIdx.x;
    const int warp = tid >> 5, lane = tid & 31;
    const int row0 = blockIdx.x * ROWS_PER_CTA;

    // ---- B fragments: W_hh fp16, resident ----
    uint32_t bf[7][2][2];
    {
        const int bn = 16 * warp + (lane >> 2);
        const int bk = 2 * (lane & 3);
#pragma unroll
        for (int c = 0; c < 7; c++) {
#pragma unroll
            for (int t = 0; t < 2; t++) {
                int n = bn + 8 * t;
#pragma unroll
                for (int rr = 0; rr < 2; rr++) {
                    int k = 16 * c + bk + 8 * rr;
                    float lo = (k     < 100) ? W_hh[k * 400 + n]       : 0.f;
                    float hi = (k + 1 < 100) ? W_hh[(k + 1) * 400 + n] : 0.f;
                    __half2 hv = __floats2half2_rn(lo, hi);
                    bf[c][t][rr] = *reinterpret_cast<uint32_t*>(&hv);
                }
            }
        }
    }

    // ---- epilogue lane constants ----
    const int erow = lane >> 2;
    const bool evalid = (erow < ROWS_PER_CTA);
    const int ecol0 = 16 * warp + 2 * (lane & 3);
    const int g0 = ecol0 / 100, g1 = (ecol0 + 8) / 100;
    const float as0 = (g0 == 2) ? 2.f : 1.f, aA0 = as0, aB0 = (g0 == 2) ? -1.f : 0.f;
    const float as1 = (g1 == 2) ? 2.f : 1.f, aA1 = as1, aB1 = (g1 == 2) ? -1.f : 0.f;
    const int eoffA = (erow < 7 ? erow : 0) * SRW + ecol0;

    const uint32_t la0 = smem_u32(hbuf + (lane & 15) * HS2 + (lane >> 4) * 8);
    const uint32_t la1 = la0 + 16 * HS2 * 2;

    const int r_2 = tid / 100, j_2 = tid % 100;
    const bool p2act = (tid < 700);
    const bool p2out = (row0 + r_2 < BATCH);
    const int p2off = r_2 * SRW + 400 + j_2;

    const bool sact = (tid < 525);
    const int r_s = tid / 75, c_s = tid % 75;
    const uint32_t stg_u32 = smem_u32(stg);

    {
        uint32_t* hz = (uint32_t*)hbuf;
        for (int i = tid; i < 1920; i += 800) hz[i] = 0u;
        for (int i = tid; i < 9200; i += 800) {
            PtS[i] = __float2half(g_Pt[i]);
            PsS[i] = __float2half(g_Ps[i]);
        }
        for (int i = tid; i < 7 * 256; i += 800) {
            int r = i >> 8, tt = i & 255;
            int rr = min(row0 + r, BATCH - 1);
            int g = rr * 256 + tt;
            trajS[i] = (uint16_t)traj[g];
            uint32_t A = (uint32_t)tu[g] | ((uint32_t)tl[g] << 8) |
                         ((uint32_t)su[g] << 16) | ((uint32_t)sl[g] << 24);
            uint32_t B = (uint32_t)tu_s[g] | ((uint32_t)tl_s[g] << 8) |
                         ((uint32_t)su_s[g] << 16) | ((uint32_t)sl_s[g] << 24);
            idx8[i] = make_uint2(A, B);
        }
    }
    __syncthreads();

#define ISSUE(TT, B3)                                                           \
    {                                                                           \
        if (sact && (TT) < TSTEPS) {                                            \
            int gidx = (int)trajS[(r_s << 8) + (TT)];                           \
            const __half* srcp = g_Gloc + (size_t)gidx * 600 + c_s * 8;         \
            uint32_t dstp = stg_u32 + (uint32_t)(((B3) * 7 + r_s) * SRW + c_s * 8) * 2; \
            asm volatile("cp.async.cg.shared.global [%0], [%1], 16;"            \
                         :: "r"(dstp), "l"(srcp) : "memory");                   \
        }                                                                       \
        asm volatile("cp.async.commit_group;" ::: "memory");                    \
    }

    ISSUE(0, 0)
    ISSUE(1, 1)
    asm volatile("cp.async.wait_group 1;" ::: "memory");
    __syncthreads();

    float creg = 0.f;
    float* outp = out + (row0 + r_2) * 100 + j_2;
    float* aw0 = acts + (erow < 7 ? erow : 0) * 400 + ecol0;
    const float* ap2 = acts + r_2 * 400 + j_2;
    __half* hn0 = hbuf + r_2 * HS2 + j_2;
    __half* hn1 = hn0 + 16 * HS2;

#define STEPT(T, LAB, B3R, B3W, HNP)                                            \
    {                                                                           \
        const __half* stgR = stg + (B3R) * (7 * SRW);                           \
        float c0[4] = {0.f, 0.f, 0.f, 0.f};                                     \
        float c1[4] = {0.f, 0.f, 0.f, 0.f};                                     \
        _Pragma("unroll")                                                       \
        for (int c = 0; c < 7; c++) {                                           \
            uint32_t a0, a1, a2, a3;                                            \
            asm volatile("ldmatrix.sync.aligned.m8n8.x4.shared.b16 "            \
                         "{%0,%1,%2,%3}, [%4];"                                 \
                         : "=r"(a0), "=r"(a1), "=r"(a2), "=r"(a3)               \
                         : "r"((LAB) + c * 32));                                \
            asm volatile("mma.sync.aligned.m16n8k16.row.col.f32.f16.f16.f32 "   \
                         "{%0,%1,%2,%3}, {%4,%5,%6,%7}, {%8,%9}, {%0,%1,%2,%3};"\
                         : "+f"(c0[0]), "+f"(c0[1]), "+f"(c0[2]), "+f"(c0[3])   \
                         : "r"(a0), "r"(a1), "r"(a2), "r"(a3),                  \
                           "r"(bf[c][0][0]), "r"(bf[c][0][1]));                 \
            asm volatile("mma.sync.aligned.m16n8k16.row.col.f32.f16.f16.f32 "   \
                         "{%0,%1,%2,%3}, {%4,%5,%6,%7}, {%8,%9}, {%0,%1,%2,%3};"\
                         : "+f"(c1[0]), "+f"(c1[1]), "+f"(c1[2]), "+f"(c1[3])   \
                         : "r"(a0), "r"(a1), "r"(a2), "r"(a3),                  \
                           "r"(bf[c][1][0]), "r"(bf[c][1][1]));                 \
        }                                                                       \
        if (evalid) {                                                           \
            float2 q0 = __half22float2(*(const __half2*)(stgR + eoffA));        \
            float2 q1 = __half22float2(*(const __half2*)(stgR + eoffA + 8));    \
            float vA = c0[0] + q0.x, vB = c0[1] + q0.y;                         \
            float vC = c1[0] + q1.x, vD = c1[1] + q1.y;                         \
            float sA = 1.f / (1.f + __expf(-as0 * vA));                         \
            float sB = 1.f / (1.f + __expf(-as0 * vB));                         \
            float sC = 1.f / (1.f + __expf(-as1 * vC));                         \
            float sD = 1.f / (1.f + __expf(-as1 * vD));                         \
            float2 e0 = make_float2(fmaf(sA, aA0, aB0), fmaf(sB, aA0, aB0));    \
            float2 e1 = make_float2(fmaf(sC, aA1, aB1), fmaf(sD, aA1, aB1));    \
            *(float2*)(aw0)     = e0;                                           \
            *(float2*)(aw0 + 8) = e1;                                           \
        }                                                                       \
        __syncthreads();                                                        \
        if (p2act) {                                                            \
            float gi = ap2[0], gf = ap2[100], gg = ap2[200], go = ap2[300];     \
            uint2 pk = idx8[(r_2 << 8) + (T)];                                  \
            int tui = pk.x & 0xff, tli = (pk.x >> 8) & 0xff;                    \
            int sui = (pk.x >> 16) & 0xff, sli = pk.x >> 24;                    \
            float utv = (float)(pk.y & 0xff), ltv = (float)((pk.y >> 8) & 0xff);\
            float usv = (float)((pk.y >> 16) & 0xff), lsv = (float)(pk.y >> 24);\
            float rdt = __fdividef(1.f, fmaxf(utv + ltv, 1.f));                 \
            float rds = __fdividef(1.f, fmaxf(usv + lsv, 1.f));                 \
            float tpre = __half2float(stgR[p2off]);                             \
            float spre = __half2float(stgR[p2off + 100]);                       \
            float pt = tpre + (utv * __half2float(PtS[tli * 100 + j_2])         \
                             + ltv * __half2float(PtS[tui * 100 + j_2])) * rdt; \
            float ps = spre + (usv * __half2float(PsS[sli * 100 + j_2])         \
                             + lsv * __half2float(PsS[sui * 100 + j_2])) * rds; \
            float tsg = sigf(pt) * sigf(ps);                                    \
            float cN = gf * creg + gi * tsg * gg;                               \
            creg = cN;                                                          \
            float h = go * tanh_fast(cN);                                       \
            *(HNP) = __float2half(h);                                           \
            if ((T) == TSTEPS - 1 && p2out) *outp = h;                          \
        }                                                                       \
        ISSUE((T) + 2, B3W)                                                     \
        asm volatile("cp.async.wait_group 1;" ::: "memory");                    \
        __syncthreads();                                                        \
    }

    int b3a = 0;
#pragma unroll 1
    for (int s = 0; s < TSTEPS / 2; s++) {
        const int t0 = 2 * s;
        const int b3b  = (b3a == 2) ? 0 : b3a + 1;
        const int b3w0 = (b3b == 2) ? 0 : b3b + 1;
        const int b3w1 = b3a;
        STEPT(t0,     la0, b3a, b3w0, hn1)
        STEPT(t0 + 1, la1, b3b, b3w1, hn0)
        b3a = b3w0;
    }
#undef STEPT
#undef ISSUE
}

// =======================================================================
// launch
// =======================================================================
extern "C" void kernel_launch(void* const* d_in, const int* in_sizes, int n_in,
                              void* d_out, int out_size)
{
    (void)in_sizes; (void)n_in; (void)out_size;
    const int*   traj    = (const int*)d_in[0];
    const int*   tu      = (const int*)d_in[3];
    const int*   tl      = (const int*)d_in[4];
    const int*   tu_s    = (const int*)d_in[5];
    const int*   tl_s    = (const int*)d_in[6];
    const int*   su      = (const int*)d_in[7];
    const int*   sl      = (const int*)d_in[8];
    const int*   su_s    = (const int*)d_in[9];
    const int*   sl_s    = (const int*)d_in[10];
    const float* emb_loc = (const float*)d_in[11];
    const float* emb_t   = (const float*)d_in[12];
    const float* emb_s   = (const float*)d_in[13];
    const float* W_ih    = (const float*)d_in[14];
    const float* W_hh    = (const float*)d_in[15];
    const float* b       = (const float*)d_in[16];
    const float* W_xt    = (const float*)d_in[17];
    const float* W_tt    = (const float*)d_in[18];
    const float* b_t     = (const float*)d_in[19];
    const float* W_xs    = (const float*)d_in[20];
    const float* W_ss    = (const float*)d_in[21];
    const float* b_s     = (const float*)d_in[22];
    float* out = (float*)d_out;

    static bool attr_set = false;
    if (!attr_set) {
        cudaFuncSetAttribute(kernD, cudaFuncAttributeMaxDynamicSharedMemorySize,
                             DSM_TOTAL);
        attr_set = true;
    }

    // P: fp16 conversion of emb_loc + fused weight matrix
    const int NP = LOCN * 28 + 112 * 152;
    kernP<<<(NP + 255) / 256, 256>>>(emb_loc, W_ih, W_xt, W_xs);

    // A: tensor-core GEMM on fp16 inputs
    dim3 gA(5, (LOCN + 63) / 64);
    kernA<<<gA, 128>>>(b, b_t, b_s);

    kernB<<<(92 * 100 * 2 + 255) / 256, 256>>>(emb_t, W_tt, emb_s, W_ss);

    kernD<<<NCTA, 800, DSM_TOTAL>>>(W_hh, out, traj,
                                    tu, tl, tu_s, tl_s, su, sl, su_s, sl_s);
}